// round 1
// baseline (speedup 1.0000x reference)
#include <cuda_runtime.h>
#include <math.h>

// Problem constants
constexpr int B_ = 2;
constexpr int S_ = 2048;
constexpr int D_ = 1024;
constexpr int H_ = 16;
constexpr int HD_ = 64;

constexpr size_t BSD  = (size_t)B_ * S_ * D_;          // 4,194,304 (out elements)
constexpr size_t BHSS = (size_t)B_ * H_ * S_ * S_;     // 134,217,728 (attn elements)

// Scratch (device globals: allocation is forbidden)
__device__ float g_Q[BSD];
__device__ float g_K[BSD];
__device__ float g_V[BSD];
__device__ float g_C[BSD];
__device__ float g_attn_fallback[BHSS];  // used only if harness out buffer lacks attn

// ---------------------------------------------------------------------------
// NT GEMM: C[M,N] = alpha * A[M,K] @ B[N,K]^T + bias[N]
// Tiles: 128x128x16, 256 threads, 8x8 per thread.
// M, N multiples of 128; K multiple of 16. No bounds checks (shapes guaranteed).
// ---------------------------------------------------------------------------
__global__ __launch_bounds__(256) void gemm_nt_proj(
    const float* __restrict__ A, const float* __restrict__ Bm,
    const float* __restrict__ bias, float* __restrict__ C,
    int K, int lda, int ldb, int ldc)
{
    __shared__ float As[16][128];
    __shared__ float Bs[16][128];
    const int tid = threadIdx.x;
    const int tx = tid & 15;   // N direction
    const int ty = tid >> 4;   // M direction
    const size_t bm = (size_t)blockIdx.y * 128;
    const size_t bn = (size_t)blockIdx.x * 128;
    const float* Ab = A + bm * lda;
    const float* Bb = Bm + bn * ldb;

    float acc[8][8];
#pragma unroll
    for (int i = 0; i < 8; i++)
#pragma unroll
        for (int j = 0; j < 8; j++) acc[i][j] = 0.f;

    const int r0 = tid >> 2;         // 0..63
    const int c4 = (tid & 3) * 4;    // 0,4,8,12

    for (int k0 = 0; k0 < K; k0 += 16) {
#pragma unroll
        for (int i = 0; i < 2; i++) {
            int r = r0 + i * 64;
            float4 a = *(const float4*)(Ab + (size_t)r * lda + k0 + c4);
            As[c4 + 0][r] = a.x; As[c4 + 1][r] = a.y;
            As[c4 + 2][r] = a.z; As[c4 + 3][r] = a.w;
            float4 b = *(const float4*)(Bb + (size_t)r * ldb + k0 + c4);
            Bs[c4 + 0][r] = b.x; Bs[c4 + 1][r] = b.y;
            Bs[c4 + 2][r] = b.z; Bs[c4 + 3][r] = b.w;
        }
        __syncthreads();
#pragma unroll
        for (int kk = 0; kk < 16; kk++) {
            float ra[8], rb[8];
#pragma unroll
            for (int i = 0; i < 8; i++) ra[i] = As[kk][ty * 8 + i];
#pragma unroll
            for (int j = 0; j < 8; j++) rb[j] = Bs[kk][tx * 8 + j];
#pragma unroll
            for (int i = 0; i < 8; i++)
#pragma unroll
                for (int j = 0; j < 8; j++) acc[i][j] += ra[i] * rb[j];
        }
        __syncthreads();
    }

#pragma unroll
    for (int i = 0; i < 8; i++) {
        size_t crow = (bm + ty * 8 + i) * (size_t)ldc + bn + tx * 8;
#pragma unroll
        for (int j = 0; j < 8; j += 4) {
            float4 o;
            o.x = acc[i][j + 0] + bias[bn + tx * 8 + j + 0];
            o.y = acc[i][j + 1] + bias[bn + tx * 8 + j + 1];
            o.z = acc[i][j + 2] + bias[bn + tx * 8 + j + 2];
            o.w = acc[i][j + 3] + bias[bn + tx * 8 + j + 3];
            *(float4*)(C + crow + j) = o;
        }
    }
}

// ---------------------------------------------------------------------------
// scores: per (b,h): logits[S,S] = (1/8) * Qh[S,64] @ Kh[S,64]^T
// Qh/Kh are column slices of [B,S,D] (lda=ldb=D). Output ldc = S.
// ---------------------------------------------------------------------------
__global__ __launch_bounds__(256) void scores_kernel(
    const float* __restrict__ Q, const float* __restrict__ K,
    float* __restrict__ attnL)
{
    __shared__ float As[16][128];
    __shared__ float Bs[16][128];
    const int z = blockIdx.z;
    const int b = z >> 4;
    const int h = z & 15;
    const float* Ab = Q + (size_t)b * S_ * D_ + h * HD_ + (size_t)blockIdx.y * 128 * D_;
    const float* Bb = K + (size_t)b * S_ * D_ + h * HD_ + (size_t)blockIdx.x * 128 * D_;
    float* C = attnL + (size_t)z * S_ * S_;

    const int tid = threadIdx.x;
    const int tx = tid & 15;
    const int ty = tid >> 4;
    const size_t bm = (size_t)blockIdx.y * 128;
    const size_t bn = (size_t)blockIdx.x * 128;

    float acc[8][8];
#pragma unroll
    for (int i = 0; i < 8; i++)
#pragma unroll
        for (int j = 0; j < 8; j++) acc[i][j] = 0.f;

    const int r0 = tid >> 2;
    const int c4 = (tid & 3) * 4;

#pragma unroll
    for (int k0 = 0; k0 < HD_; k0 += 16) {
#pragma unroll
        for (int i = 0; i < 2; i++) {
            int r = r0 + i * 64;
            float4 a = *(const float4*)(Ab + (size_t)r * D_ + k0 + c4);
            As[c4 + 0][r] = a.x; As[c4 + 1][r] = a.y;
            As[c4 + 2][r] = a.z; As[c4 + 3][r] = a.w;
            float4 bv = *(const float4*)(Bb + (size_t)r * D_ + k0 + c4);
            Bs[c4 + 0][r] = bv.x; Bs[c4 + 1][r] = bv.y;
            Bs[c4 + 2][r] = bv.z; Bs[c4 + 3][r] = bv.w;
        }
        __syncthreads();
#pragma unroll
        for (int kk = 0; kk < 16; kk++) {
            float ra[8], rb[8];
#pragma unroll
            for (int i = 0; i < 8; i++) ra[i] = As[kk][ty * 8 + i];
#pragma unroll
            for (int j = 0; j < 8; j++) rb[j] = Bs[kk][tx * 8 + j];
#pragma unroll
            for (int i = 0; i < 8; i++)
#pragma unroll
                for (int j = 0; j < 8; j++) acc[i][j] += ra[i] * rb[j];
        }
        __syncthreads();
    }

    const float scale = 0.125f;  // 1/sqrt(64)
#pragma unroll
    for (int i = 0; i < 8; i++) {
        size_t crow = (bm + ty * 8 + i) * (size_t)S_ + bn + tx * 8;
#pragma unroll
        for (int j = 0; j < 8; j += 4) {
            float4 o;
            o.x = acc[i][j + 0] * scale;
            o.y = acc[i][j + 1] * scale;
            o.z = acc[i][j + 2] * scale;
            o.w = acc[i][j + 3] * scale;
            *(float4*)(C + crow + j) = o;
        }
    }
}

// ---------------------------------------------------------------------------
// Row softmax in place. One block (256 threads) per row of 2048.
// ---------------------------------------------------------------------------
__global__ __launch_bounds__(256) void softmax_kernel(float* __restrict__ attn)
{
    float* x = attn + (size_t)blockIdx.x * S_;
    const int tid = threadIdx.x;
    float v[8];
    float m = -3.4e38f;
#pragma unroll
    for (int i = 0; i < 8; i++) {
        v[i] = x[tid + i * 256];
        m = fmaxf(m, v[i]);
    }
#pragma unroll
    for (int o = 16; o; o >>= 1) m = fmaxf(m, __shfl_xor_sync(0xffffffffu, m, o));
    __shared__ float sred[8];
    if ((tid & 31) == 0) sred[tid >> 5] = m;
    __syncthreads();
    m = sred[0];
#pragma unroll
    for (int w = 1; w < 8; w++) m = fmaxf(m, sred[w]);
    __syncthreads();

    float s = 0.f;
#pragma unroll
    for (int i = 0; i < 8; i++) {
        v[i] = __expf(v[i] - m);
        s += v[i];
    }
#pragma unroll
    for (int o = 16; o; o >>= 1) s += __shfl_xor_sync(0xffffffffu, s, o);
    if ((tid & 31) == 0) sred[tid >> 5] = s;
    __syncthreads();
    s = sred[0];
#pragma unroll
    for (int w = 1; w < 8; w++) s += sred[w];
    const float inv = 1.f / s;
#pragma unroll
    for (int i = 0; i < 8; i++) x[tid + i * 256] = v[i] * inv;
}

// ---------------------------------------------------------------------------
// ctx: per (b,h): Ch[S,64] = P[S,S] @ Vh[S,64]   (NN GEMM)
// Tiles 128x64x16, 256 threads, 8x4 per thread.
// ---------------------------------------------------------------------------
__global__ __launch_bounds__(256) void ctx_kernel(
    const float* __restrict__ attn, const float* __restrict__ V,
    float* __restrict__ Cg)
{
    __shared__ float As[16][128];
    __shared__ float Bs[16][64];
    const int z = blockIdx.z;
    const int b = z >> 4;
    const int h = z & 15;
    const float* A  = attn + (size_t)z * S_ * S_;
    const float* Bp = V + (size_t)b * S_ * D_ + h * HD_;
    float* C = Cg + (size_t)b * S_ * D_ + h * HD_;

    const int tid = threadIdx.x;
    const int tx = tid & 15;   // N: tx*4
    const int ty = tid >> 4;   // M: ty*8
    const size_t bm = (size_t)blockIdx.y * 128;

    float acc[8][4];
#pragma unroll
    for (int i = 0; i < 8; i++)
#pragma unroll
        for (int j = 0; j < 4; j++) acc[i][j] = 0.f;

    const int r0 = tid >> 2;
    const int c4 = (tid & 3) * 4;
    const int br  = tid >> 4;          // 0..15
    const int bc4 = (tid & 15) * 4;    // 0..60

    for (int k0 = 0; k0 < S_; k0 += 16) {
#pragma unroll
        for (int i = 0; i < 2; i++) {
            int r = r0 + i * 64;
            float4 a = *(const float4*)(A + (bm + r) * (size_t)S_ + k0 + c4);
            As[c4 + 0][r] = a.x; As[c4 + 1][r] = a.y;
            As[c4 + 2][r] = a.z; As[c4 + 3][r] = a.w;
        }
        float4 bv = *(const float4*)(Bp + (size_t)(k0 + br) * D_ + bc4);
        *(float4*)&Bs[br][bc4] = bv;
        __syncthreads();
#pragma unroll
        for (int kk = 0; kk < 16; kk++) {
            float ra[8], rb[4];
#pragma unroll
            for (int i = 0; i < 8; i++) ra[i] = As[kk][ty * 8 + i];
#pragma unroll
            for (int j = 0; j < 4; j++) rb[j] = Bs[kk][tx * 4 + j];
#pragma unroll
            for (int i = 0; i < 8; i++)
#pragma unroll
                for (int j = 0; j < 4; j++) acc[i][j] += ra[i] * rb[j];
        }
        __syncthreads();
    }

#pragma unroll
    for (int i = 0; i < 8; i++) {
        float4 o;
        o.x = acc[i][0]; o.y = acc[i][1]; o.z = acc[i][2]; o.w = acc[i][3];
        *(float4*)(C + (bm + ty * 8 + i) * (size_t)D_ + tx * 4) = o;
    }
}

// ---------------------------------------------------------------------------
extern "C" void kernel_launch(void* const* d_in, const int* in_sizes, int n_in,
                              void* d_out, int out_size)
{
    const float* x  = (const float*)d_in[0];
    const float* Wq = (const float*)d_in[1];
    const float* bq = (const float*)d_in[2];
    const float* Wk = (const float*)d_in[3];
    const float* bk = (const float*)d_in[4];
    const float* Wv = (const float*)d_in[5];
    const float* bv = (const float*)d_in[6];
    const float* Wo = (const float*)d_in[7];
    const float* bo = (const float*)d_in[8];

    float* out = (float*)d_out;

    float *Qp, *Kp, *Vp, *Cp;
    cudaGetSymbolAddress((void**)&Qp, g_Q);
    cudaGetSymbolAddress((void**)&Kp, g_K);
    cudaGetSymbolAddress((void**)&Vp, g_V);
    cudaGetSymbolAddress((void**)&Cp, g_C);

    float* attn;
    if ((size_t)out_size >= BSD + BHSS) {
        attn = out + BSD;  // harness buffer holds (out, attn) concatenated
    } else {
        cudaGetSymbolAddress((void**)&attn, g_attn_fallback);
    }

    // 1) Q/K/V projections: [4096,1024] = x @ W^T + b
    dim3 gproj(D_ / 128, (B_ * S_) / 128);  // (8, 32)
    gemm_nt_proj<<<gproj, 256>>>(x, Wq, bq, Qp, D_, D_, D_, D_);
    gemm_nt_proj<<<gproj, 256>>>(x, Wk, bk, Kp, D_, D_, D_, D_);
    gemm_nt_proj<<<gproj, 256>>>(x, Wv, bv, Vp, D_, D_, D_, D_);

    // 2) scores = scale * Q K^T  -> attn buffer (logits)
    dim3 gsc(S_ / 128, S_ / 128, B_ * H_);  // (16,16,32)
    scores_kernel<<<gsc, 256>>>(Qp, Kp, attn);

    // 3) row softmax in place
    softmax_kernel<<<B_ * H_ * S_, 256>>>(attn);

    // 4) ctx = attn @ V  -> g_C laid out as [B,S,D]
    dim3 gcx(1, S_ / 128, B_ * H_);  // (1,16,32)
    ctx_kernel<<<gcx, 256>>>(attn, Vp, Cp);

    // 5) out = ctx @ Wo^T + bo
    gemm_nt_proj<<<gproj, 256>>>(Cp, Wo, bo, out, D_, D_, D_, D_);
}

// round 2
// speedup vs baseline: 2.7031x; 2.7031x over previous
#include <cuda_runtime.h>
#include <math.h>
#include <stdint.h>

// Problem constants
constexpr int B_ = 2;
constexpr int S_ = 2048;
constexpr int D_ = 1024;
constexpr int H_ = 16;
constexpr int HD_ = 64;

constexpr size_t BSD  = (size_t)B_ * S_ * D_;          // 4,194,304
constexpr size_t BHSS = (size_t)B_ * H_ * S_ * S_;     // 134,217,728

// Scratch (device globals: allocation is forbidden)
__device__ float g_Q[BSD];
__device__ float g_K[BSD];
__device__ float g_V[BSD];
__device__ float g_C[BSD];
__device__ float g_attn_fallback[BHSS];

// ---------------------------------------------------------------------------
// Helpers
// ---------------------------------------------------------------------------
__device__ __forceinline__ uint32_t f2tf(float f) {
    uint32_t u;
    asm("cvt.rna.tf32.f32 %0, %1;" : "=r"(u) : "f"(f));
    return u;
}

__device__ __forceinline__ void mma8(float* c, const uint32_t* a, const uint32_t* b) {
    asm volatile(
        "mma.sync.aligned.m16n8k8.row.col.f32.tf32.tf32.f32 "
        "{%0,%1,%2,%3},{%4,%5,%6,%7},{%8,%9},{%0,%1,%2,%3};"
        : "+f"(c[0]), "+f"(c[1]), "+f"(c[2]), "+f"(c[3])
        : "r"(a[0]), "r"(a[1]), "r"(a[2]), "r"(a[3]), "r"(b[0]), "r"(b[1]));
}

__device__ __forceinline__ void cp16(uint32_t saddr, const void* gaddr) {
    asm volatile("cp.async.cg.shared.global [%0], [%1], 16;" :: "r"(saddr), "l"(gaddr));
}
__device__ __forceinline__ void cp_commit() {
    asm volatile("cp.async.commit_group;");
}
template <int N>
__device__ __forceinline__ void cp_wait() {
    asm volatile("cp.async.wait_group %0;" :: "n"(N));
}

// ---------------------------------------------------------------------------
// Generic pipelined tf32 tensor-core GEMM.
//   NT mode (NT=true):  C[M,BN-col block] = alpha*A[M,K] @ Bmat[N,K]^T (+bias)
//   NN mode (NT=false): C = alpha*A[M,K] @ Bmat[K,N]                  (+bias)
// CTA tile: 128 x BN, K-tile 32, 256 threads (8 warps: 4 in M x 2 in N).
// ZMODE: 0 = plain (proj), 1 = scores (per b,h head slices), 2 = ctx.
// ---------------------------------------------------------------------------
template <int BN, bool NT, int ZMODE>
__global__ __launch_bounds__(256, 2) void mma_gemm(
    const float* __restrict__ Ag, const float* __restrict__ Bg,
    const float* __restrict__ bias, float* __restrict__ Cg,
    int K, int lda, int ldb, int ldc, float alpha)
{
    constexpr int A_LD = 36;                 // 32 k + 4 pad (words)
    constexpr int A_WORDS = 128 * A_LD;
    constexpr int BNT_LD = 36;
    constexpr int BNN_LD = 72;               // 64 n + 8 pad
    constexpr int B_WORDS = NT ? (BN * BNT_LD) : (32 * BNN_LD);
    constexpr int STAGE = A_WORDS + B_WORDS;
    constexpr int NS = 3;                    // pipeline stages

    extern __shared__ float smem[];

    const int tid = threadIdx.x;
    const int z = blockIdx.z;

    const float* A;
    const float* Bp;
    float* C;
    if (ZMODE == 0) {
        A = Ag; Bp = Bg; C = Cg;
    } else if (ZMODE == 1) {  // scores: Q,K head slices -> attn logits
        int b = z >> 4, h = z & 15;
        A  = Ag + (size_t)b * S_ * D_ + h * HD_;
        Bp = Bg + (size_t)b * S_ * D_ + h * HD_;
        C  = Cg + (size_t)z * S_ * S_;
    } else {                  // ctx: attn @ V head slice
        int b = z >> 4, h = z & 15;
        A  = Ag + (size_t)z * S_ * S_;
        Bp = Bg + (size_t)b * S_ * D_ + h * HD_;
        C  = Cg + (size_t)b * S_ * D_ + h * HD_;
    }

    const size_t bm = (size_t)blockIdx.y * 128;
    const size_t bn = (size_t)blockIdx.x * BN;

    const int T = K / 32;  // number of K tiles

    // cp.async issue for one K-tile (k0 = t*32) into stage buffer s
    auto issue = [&](int t, int s) {
        const int k0 = t * 32;
        float* As = smem + s * STAGE;
        float* Bs = As + A_WORDS;
        // A tile: 128 rows x 32 k, natural [m][k] layout
#pragma unroll
        for (int i = 0; i < 4; i++) {
            int f = tid + 256 * i;          // 0..1023 float4s
            int m = f >> 3;
            int kc = (f & 7) * 4;
            uint32_t d = (uint32_t)__cvta_generic_to_shared(As + m * A_LD + kc);
            cp16(d, A + (bm + m) * (size_t)lda + k0 + kc);
        }
        if (NT) {
            // B tile: BN rows x 32 k, [n][k]
#pragma unroll
            for (int i = 0; i < BN / 32; i++) {
                int f = tid + 256 * i;
                int n = f >> 3;
                int kc = (f & 7) * 4;
                uint32_t d = (uint32_t)__cvta_generic_to_shared(Bs + n * BNT_LD + kc);
                cp16(d, Bp + (bn + n) * (size_t)ldb + k0 + kc);
            }
        } else {
            // B tile: 32 k-rows x 64 n, [k][n]
#pragma unroll
            for (int i = 0; i < 2; i++) {
                int f = tid + 256 * i;       // 0..511 float4s
                int kr = f >> 4;
                int nc = (f & 15) * 4;
                uint32_t d = (uint32_t)__cvta_generic_to_shared(Bs + kr * BNN_LD + nc);
                cp16(d, Bp + (size_t)(k0 + kr) * ldb + bn + nc);
            }
        }
    };

    // Prologue: issue first NS-1 tiles
#pragma unroll
    for (int s = 0; s < NS - 1; s++) {
        if (s < T) issue(s, s);
        cp_commit();
    }

    const int warp = tid >> 5, lane = tid & 31;
    const int wm = (warp >> 1) * 32;          // warp M offset (0,32,64,96)
    const int wn = (warp & 1) * (BN / 2);     // warp N offset
    const int grp = lane >> 2, qid = lane & 3;
    constexpr int NTI = BN / 16;              // B 8-col tiles per warp (8 or 4)

    float acc[2][NTI][4];
#pragma unroll
    for (int i = 0; i < 2; i++)
#pragma unroll
        for (int j = 0; j < NTI; j++)
#pragma unroll
            for (int r = 0; r < 4; r++) acc[i][j][r] = 0.f;

    for (int t = 0; t < T; t++) {
        cp_wait<NS - 2>();
        __syncthreads();

        const float* As = smem + (t % NS) * STAGE;
        const float* Bs = As + A_WORDS;

#pragma unroll
        for (int ks = 0; ks < 4; ks++) {
            uint32_t afr[2][4];
#pragma unroll
            for (int i = 0; i < 2; i++) {
                const float* ap = As + (wm + 16 * i + grp) * A_LD + 8 * ks + qid;
                afr[i][0] = f2tf(ap[0]);
                afr[i][1] = f2tf(ap[8 * A_LD]);
                afr[i][2] = f2tf(ap[4]);
                afr[i][3] = f2tf(ap[8 * A_LD + 4]);
            }
            uint32_t bfr[NTI][2];
#pragma unroll
            for (int j = 0; j < NTI; j++) {
                if (NT) {
                    const float* bp = Bs + (wn + 8 * j + grp) * BNT_LD + 8 * ks + qid;
                    bfr[j][0] = f2tf(bp[0]);
                    bfr[j][1] = f2tf(bp[4]);
                } else {
                    const float* bp = Bs + (8 * ks + qid) * BNN_LD + wn + 8 * j + grp;
                    bfr[j][0] = f2tf(bp[0]);
                    bfr[j][1] = f2tf(bp[4 * BNN_LD]);
                }
            }
#pragma unroll
            for (int i = 0; i < 2; i++)
#pragma unroll
                for (int j = 0; j < NTI; j++)
                    mma8(acc[i][j], afr[i], bfr[j]);
        }

        if (t + NS - 1 < T) issue(t + NS - 1, (t + NS - 1) % NS);
        cp_commit();
    }

    // Epilogue: c0/c1 at (row, col..col+1), c2/c3 at (row+8, col..col+1)
#pragma unroll
    for (int i = 0; i < 2; i++) {
#pragma unroll
        for (int j = 0; j < NTI; j++) {
            size_t row = bm + wm + 16 * i + grp;
            size_t col = bn + wn + 8 * j + 2 * qid;
            float bx = 0.f, by = 0.f;
            if (bias) { bx = bias[col]; by = bias[col + 1]; }
            float2 v0 = make_float2(acc[i][j][0] * alpha + bx,
                                    acc[i][j][1] * alpha + by);
            float2 v1 = make_float2(acc[i][j][2] * alpha + bx,
                                    acc[i][j][3] * alpha + by);
            *(float2*)(C + row * (size_t)ldc + col) = v0;
            *(float2*)(C + (row + 8) * (size_t)ldc + col) = v1;
        }
    }
}

// ---------------------------------------------------------------------------
// Row softmax in place. One block (256 threads) per row of 2048.
// ---------------------------------------------------------------------------
__global__ __launch_bounds__(256) void softmax_kernel(float* __restrict__ attn)
{
    float* x = attn + (size_t)blockIdx.x * S_;
    const int tid = threadIdx.x;
    float v[8];
    float m = -3.4e38f;
#pragma unroll
    for (int i = 0; i < 8; i++) {
        v[i] = x[tid + i * 256];
        m = fmaxf(m, v[i]);
    }
#pragma unroll
    for (int o = 16; o; o >>= 1) m = fmaxf(m, __shfl_xor_sync(0xffffffffu, m, o));
    __shared__ float sred[8];
    if ((tid & 31) == 0) sred[tid >> 5] = m;
    __syncthreads();
    m = sred[0];
#pragma unroll
    for (int w = 1; w < 8; w++) m = fmaxf(m, sred[w]);
    __syncthreads();

    float s = 0.f;
#pragma unroll
    for (int i = 0; i < 8; i++) {
        v[i] = __expf(v[i] - m);
        s += v[i];
    }
#pragma unroll
    for (int o = 16; o; o >>= 1) s += __shfl_xor_sync(0xffffffffu, s, o);
    if ((tid & 31) == 0) sred[tid >> 5] = s;
    __syncthreads();
    s = sred[0];
#pragma unroll
    for (int w = 1; w < 8; w++) s += sred[w];
    const float inv = 1.f / s;
#pragma unroll
    for (int i = 0; i < 8; i++) x[tid + i * 256] = v[i] * inv;
}

// ---------------------------------------------------------------------------
extern "C" void kernel_launch(void* const* d_in, const int* in_sizes, int n_in,
                              void* d_out, int out_size)
{
    const float* x  = (const float*)d_in[0];
    const float* Wq = (const float*)d_in[1];
    const float* bq = (const float*)d_in[2];
    const float* Wk = (const float*)d_in[3];
    const float* bk = (const float*)d_in[4];
    const float* Wv = (const float*)d_in[5];
    const float* bv = (const float*)d_in[6];
    const float* Wo = (const float*)d_in[7];
    const float* bo = (const float*)d_in[8];

    float* out = (float*)d_out;

    float *Qp, *Kp, *Vp, *Cp;
    cudaGetSymbolAddress((void**)&Qp, g_Q);
    cudaGetSymbolAddress((void**)&Kp, g_K);
    cudaGetSymbolAddress((void**)&Vp, g_V);
    cudaGetSymbolAddress((void**)&Cp, g_C);

    float* attn;
    if ((size_t)out_size >= BSD + BHSS) {
        attn = out + BSD;
    } else {
        cudaGetSymbolAddress((void**)&attn, g_attn_fallback);
    }

    constexpr int SMEM_NT  = 3 * (128 * 36 + 128 * 36) * 4;  // 110592 B
    constexpr int SMEM_CTX = 3 * (128 * 36 + 32 * 72) * 4;   // 82944 B

    cudaFuncSetAttribute(mma_gemm<128, true, 0>,
                         cudaFuncAttributeMaxDynamicSharedMemorySize, SMEM_NT);
    cudaFuncSetAttribute(mma_gemm<128, true, 1>,
                         cudaFuncAttributeMaxDynamicSharedMemorySize, SMEM_NT);
    cudaFuncSetAttribute(mma_gemm<64, false, 2>,
                         cudaFuncAttributeMaxDynamicSharedMemorySize, SMEM_CTX);

    // 1) Q/K/V projections: [4096,1024] = x @ W^T + b
    dim3 gproj(D_ / 128, (B_ * S_) / 128);  // (8, 32)
    mma_gemm<128, true, 0><<<gproj, 256, SMEM_NT>>>(x, Wq, bq, Qp, D_, D_, D_, D_, 1.f);
    mma_gemm<128, true, 0><<<gproj, 256, SMEM_NT>>>(x, Wk, bk, Kp, D_, D_, D_, D_, 1.f);
    mma_gemm<128, true, 0><<<gproj, 256, SMEM_NT>>>(x, Wv, bv, Vp, D_, D_, D_, D_, 1.f);

    // 2) scores = 0.125 * Q K^T  -> attn logits
    dim3 gsc(S_ / 128, S_ / 128, B_ * H_);  // (16,16,32)
    mma_gemm<128, true, 1><<<gsc, 256, SMEM_NT>>>(Qp, Kp, nullptr, attn,
                                                  HD_, D_, D_, S_, 0.125f);

    // 3) row softmax in place
    softmax_kernel<<<B_ * H_ * S_, 256>>>(attn);

    // 4) ctx = attn @ V
    dim3 gcx(1, S_ / 128, B_ * H_);  // (1,16,32)
    mma_gemm<64, false, 2><<<gcx, 256, SMEM_CTX>>>(attn, Vp, nullptr, Cp,
                                                   S_, S_, D_, D_, 1.f);

    // 5) out = ctx @ Wo^T + bo
    mma_gemm<128, true, 0><<<gproj, 256, SMEM_NT>>>(Cp, Wo, bo, out, D_, D_, D_, D_, 1.f);
}

// round 3
// speedup vs baseline: 2.9596x; 1.0949x over previous
#include <cuda_runtime.h>
#include <math.h>
#include <stdint.h>

// Problem constants
constexpr int B_ = 2;
constexpr int S_ = 2048;
constexpr int D_ = 1024;
constexpr int H_ = 16;
constexpr int HD_ = 64;

constexpr size_t BSD  = (size_t)B_ * S_ * D_;          // 4,194,304
constexpr size_t BHSS = (size_t)B_ * H_ * S_ * S_;     // 134,217,728

// Scratch (device globals: allocation is forbidden)
__device__ float g_Q[BSD];
__device__ float g_K[BSD];
__device__ float g_V[BSD];
__device__ float g_C[BSD];
__device__ float g_X[BSD];                 // tf32-rounded x
__device__ float g_Wr[4 * D_ * D_];        // tf32-rounded Wq,Wk,Wv,Wo
__device__ float g_attn_fallback[BHSS];

// ---------------------------------------------------------------------------
// Helpers
// ---------------------------------------------------------------------------
__device__ __forceinline__ uint32_t f2tf(float f) {
    uint32_t u;
    asm("cvt.rna.tf32.f32 %0, %1;" : "=r"(u) : "f"(f));
    return u;
}

__device__ __forceinline__ void mma8(float* c, const uint32_t* a, const uint32_t* b) {
    asm volatile(
        "mma.sync.aligned.m16n8k8.row.col.f32.tf32.tf32.f32 "
        "{%0,%1,%2,%3},{%4,%5,%6,%7},{%8,%9},{%0,%1,%2,%3};"
        : "+f"(c[0]), "+f"(c[1]), "+f"(c[2]), "+f"(c[3])
        : "r"(a[0]), "r"(a[1]), "r"(a[2]), "r"(a[3]), "r"(b[0]), "r"(b[1]));
}

__device__ __forceinline__ void cp16(uint32_t saddr, const void* gaddr) {
    asm volatile("cp.async.cg.shared.global [%0], [%1], 16;" :: "r"(saddr), "l"(gaddr));
}
__device__ __forceinline__ void cp_commit() {
    asm volatile("cp.async.commit_group;");
}
template <int N>
__device__ __forceinline__ void cp_wait() {
    asm volatile("cp.async.wait_group %0;" :: "n"(N));
}

__device__ __forceinline__ uint32_t fbits(float f) { return __float_as_uint(f); }

// ---------------------------------------------------------------------------
// tf32 pre-round kernel (elementwise, float4)
// ---------------------------------------------------------------------------
__global__ void round_kernel(const float4* __restrict__ in, float4* __restrict__ out, int n4)
{
    int i = blockIdx.x * blockDim.x + threadIdx.x;
    if (i < n4) {
        float4 v = in[i];
        float4 o;
        o.x = __uint_as_float(f2tf(v.x));
        o.y = __uint_as_float(f2tf(v.y));
        o.z = __uint_as_float(f2tf(v.z));
        o.w = __uint_as_float(f2tf(v.w));
        out[i] = o;
    }
}

// ---------------------------------------------------------------------------
// NT projection GEMM: C[M,N] = alpha*(A[M,K] @ Bm[N,K]^T + bias[N])
// Inputs already tf32-rounded -> no cvt in mainloop.
// Tile 128x128x32, 256 threads (4x2 warps), 3-stage cp.async pipeline.
// ROUND: round outputs to tf32 (for tensors feeding later mmas).
// ---------------------------------------------------------------------------
template <bool ROUND>
__global__ __launch_bounds__(256, 2) void proj_gemm(
    const float* __restrict__ A, const float* __restrict__ Bm,
    const float* __restrict__ bias, float* __restrict__ C,
    int K, float alpha)
{
    constexpr int LD = 36;
    constexpr int A_WORDS = 128 * LD;
    constexpr int STAGE = 2 * A_WORDS;
    constexpr int NS = 3;
    extern __shared__ float smem[];

    const int tid = threadIdx.x;
    const size_t bm = (size_t)blockIdx.y * 128;
    const size_t bn = (size_t)blockIdx.x * 128;
    const int T = K / 32;

    auto issue = [&](int t, int s) {
        const int k0 = t * 32;
        float* As = smem + s * STAGE;
        float* Bs = As + A_WORDS;
#pragma unroll
        for (int i = 0; i < 4; i++) {
            int f = tid + 256 * i;
            int m = f >> 3;
            int kc = (f & 7) * 4;
            cp16((uint32_t)__cvta_generic_to_shared(As + m * LD + kc),
                 A + (bm + m) * (size_t)D_ + k0 + kc);
            cp16((uint32_t)__cvta_generic_to_shared(Bs + m * LD + kc),
                 Bm + (bn + m) * (size_t)D_ + k0 + kc);
        }
    };

#pragma unroll
    for (int s = 0; s < NS - 1; s++) {
        issue(s, s);
        cp_commit();
    }

    const int warp = tid >> 5, lane = tid & 31;
    const int wm = (warp >> 1) * 32;
    const int wn = (warp & 1) * 64;
    const int grp = lane >> 2, qid = lane & 3;

    float acc[2][8][4];
#pragma unroll
    for (int i = 0; i < 2; i++)
#pragma unroll
        for (int j = 0; j < 8; j++)
#pragma unroll
            for (int r = 0; r < 4; r++) acc[i][j][r] = 0.f;

    for (int t = 0; t < T; t++) {
        cp_wait<NS - 2>();
        __syncthreads();
        const float* As = smem + (t % NS) * STAGE;
        const float* Bs = As + A_WORDS;

#pragma unroll
        for (int ks = 0; ks < 4; ks++) {
            uint32_t afr[2][4];
#pragma unroll
            for (int i = 0; i < 2; i++) {
                const float* ap = As + (wm + 16 * i + grp) * LD + 8 * ks + qid;
                afr[i][0] = fbits(ap[0]);
                afr[i][1] = fbits(ap[8 * LD]);
                afr[i][2] = fbits(ap[4]);
                afr[i][3] = fbits(ap[8 * LD + 4]);
            }
#pragma unroll
            for (int j = 0; j < 8; j++) {
                const float* bp = Bs + (wn + 8 * j + grp) * LD + 8 * ks + qid;
                uint32_t bfr[2] = {fbits(bp[0]), fbits(bp[4])};
#pragma unroll
                for (int i = 0; i < 2; i++) mma8(acc[i][j], afr[i], bfr);
            }
        }
        if (t + NS - 1 < T) issue(t + NS - 1, (t + NS - 1) % NS);
        cp_commit();
        __syncthreads();
    }

#pragma unroll
    for (int i = 0; i < 2; i++) {
#pragma unroll
        for (int j = 0; j < 8; j++) {
            size_t row = bm + wm + 16 * i + grp;
            size_t col = bn + wn + 8 * j + 2 * qid;
            float bx = bias[col], by = bias[col + 1];
            float v0 = (acc[i][j][0] + bx) * alpha;
            float v1 = (acc[i][j][1] + by) * alpha;
            float v2 = (acc[i][j][2] + bx) * alpha;
            float v3 = (acc[i][j][3] + by) * alpha;
            if (ROUND) {
                v0 = __uint_as_float(f2tf(v0));
                v1 = __uint_as_float(f2tf(v1));
                v2 = __uint_as_float(f2tf(v2));
                v3 = __uint_as_float(f2tf(v3));
            }
            *(float2*)(C + row * (size_t)D_ + col) = make_float2(v0, v1);
            *(float2*)(C + (row + 8) * (size_t)D_ + col) = make_float2(v2, v3);
        }
    }
}

// ---------------------------------------------------------------------------
// Fused attention: per CTA = (b,h) x 128 query rows.
//   Pass A: stream 16 K-tiles, S=Q@K^T via mma, accumulate row sums of exp(S).
//   Pass B: recompute S, p = exp(S)*invsum -> write attn (once) + smem P,
//           ctx += P @ V via mma. No softmax kernel, no attn re-read.
// Q pre-scaled by 0.125 at projection. No max subtraction (logits bounded).
// ---------------------------------------------------------------------------
constexpr int LDQ = 68;
constexpr int LDK = 68;
constexpr int LDV = 72;
constexpr int LDP = 132;
constexpr int SM_Q = 128 * LDQ;            // 8704
constexpr int SM_K = 2 * 128 * LDK;        // 17408
constexpr int SM_V = 128 * LDV;            // 9216
constexpr int SM_P = 128 * LDP;            // 16896
constexpr int SM_RED = 256;
constexpr int SM_ATT_WORDS = SM_Q + SM_K + SM_V + SM_P + SM_RED;  // 52480
constexpr int SM_ATT_BYTES = SM_ATT_WORDS * 4;                    // 209920

__global__ __launch_bounds__(256, 1) void attn_fused(
    const float* __restrict__ Q, const float* __restrict__ K,
    const float* __restrict__ V, float* __restrict__ attn,
    float* __restrict__ ctx)
{
    extern __shared__ float sm[];
    float* sQ = sm;
    float* sK = sQ + SM_Q;
    float* sV = sK + SM_K;
    float* sP = sV + SM_V;
    float* sRed = sP + SM_P;

    const int tid = threadIdx.x;
    const int warp = tid >> 5, lane = tid & 31;
    const int grp = lane >> 2, qid = lane & 3;
    const int wm = (warp >> 1) * 32;
    const int wn = (warp & 1) * 64;    // key-column half for S
    const int wn2 = (warp & 1) * 32;   // V-column half for ctx

    const int z = blockIdx.y;
    const int b = z >> 4, h = z & 15;
    const size_t rowbase = (size_t)blockIdx.x * 128;
    const float* Qg = Q + (size_t)b * S_ * D_ + h * HD_ + rowbase * D_;
    const float* Kg = K + (size_t)b * S_ * D_ + h * HD_;
    const float* Vg = V + (size_t)b * S_ * D_ + h * HD_;
    float* attng = attn + (size_t)z * S_ * S_ + rowbase * S_;

    auto issueQ = [&]() {
#pragma unroll
        for (int i = 0; i < 8; i++) {
            int f = tid + 256 * i;
            int r = f >> 4;
            int c = (f & 15) * 4;
            cp16((uint32_t)__cvta_generic_to_shared(sQ + r * LDQ + c),
                 Qg + (size_t)r * D_ + c);
        }
    };
    auto issueK = [&](int j, int buf) {
        float* dst = sK + buf * 128 * LDK;
        const float* src = Kg + (size_t)j * 128 * D_;
#pragma unroll
        for (int i = 0; i < 8; i++) {
            int f = tid + 256 * i;
            int r = f >> 4;
            int c = (f & 15) * 4;
            cp16((uint32_t)__cvta_generic_to_shared(dst + r * LDK + c),
                 src + (size_t)r * D_ + c);
        }
    };
    auto issueV = [&](int j) {
        const float* src = Vg + (size_t)j * 128 * D_;
#pragma unroll
        for (int i = 0; i < 8; i++) {
            int f = tid + 256 * i;
            int r = f >> 4;
            int c = (f & 15) * 4;
            cp16((uint32_t)__cvta_generic_to_shared(sV + r * LDV + c),
                 src + (size_t)r * D_ + c);
        }
    };

    // S-tile mma into sa (per warp: 32 rows x 64 key-cols)
    float sa[2][8][4];
    auto smma = [&](const float* Ks) {
#pragma unroll
        for (int i = 0; i < 2; i++)
#pragma unroll
            for (int j = 0; j < 8; j++)
#pragma unroll
                for (int r = 0; r < 4; r++) sa[i][j][r] = 0.f;
#pragma unroll
        for (int ks = 0; ks < 8; ks++) {
            uint32_t afr[2][4];
#pragma unroll
            for (int i = 0; i < 2; i++) {
                const float* ap = sQ + (wm + 16 * i + grp) * LDQ + 8 * ks + qid;
                afr[i][0] = fbits(ap[0]);
                afr[i][1] = fbits(ap[8 * LDQ]);
                afr[i][2] = fbits(ap[4]);
                afr[i][3] = fbits(ap[8 * LDQ + 4]);
            }
#pragma unroll
            for (int j = 0; j < 8; j++) {
                const float* bp = Ks + (wn + 8 * j + grp) * LDK + 8 * ks + qid;
                uint32_t bfr[2] = {fbits(bp[0]), fbits(bp[4])};
#pragma unroll
                for (int i = 0; i < 2; i++) mma8(sa[i][j], afr[i], bfr);
            }
        }
    };

    // ---------------- Pass A: row sums of exp(S) ----------------
    issueQ();
    issueK(0, 0);
    cp_commit();

    float rsum[4] = {0.f, 0.f, 0.f, 0.f};  // rows: wm+grp, wm+grp+8, wm+16+grp, wm+24+grp

    for (int j = 0; j < 16; j++) {
        if (j < 15) {
            issueK(j + 1, (j + 1) & 1);
            cp_commit();
            cp_wait<1>();
        } else {
            cp_wait<0>();
        }
        __syncthreads();
        smma(sK + (j & 1) * 128 * LDK);
#pragma unroll
        for (int i = 0; i < 2; i++)
#pragma unroll
            for (int t = 0; t < 8; t++) {
                rsum[i * 2 + 0] += __expf(sa[i][t][0]) + __expf(sa[i][t][1]);
                rsum[i * 2 + 1] += __expf(sa[i][t][2]) + __expf(sa[i][t][3]);
            }
        __syncthreads();
    }

    // reduce over qid lanes, then across the 2 warp-columns via smem
#pragma unroll
    for (int r = 0; r < 4; r++) {
        rsum[r] += __shfl_xor_sync(0xffffffffu, rsum[r], 1);
        rsum[r] += __shfl_xor_sync(0xffffffffu, rsum[r], 2);
    }
    if (qid == 0) {
#pragma unroll
        for (int r = 0; r < 4; r++) {
            int row = wm + (r >> 1) * 16 + (r & 1) * 8 + grp;
            sRed[row * 2 + (warp & 1)] = rsum[r];
        }
    }
    __syncthreads();
    float rinv[4];
#pragma unroll
    for (int r = 0; r < 4; r++) {
        int row = wm + (r >> 1) * 16 + (r & 1) * 8 + grp;
        rinv[r] = 1.f / (sRed[row * 2] + sRed[row * 2 + 1]);
    }
    __syncthreads();

    // ---------------- Pass B: write attn + ctx = P @ V ----------------
    issueK(0, 0);
    cp_commit();
    issueV(0);
    cp_commit();

    float cacc[2][4][4];
#pragma unroll
    for (int i = 0; i < 2; i++)
#pragma unroll
        for (int j = 0; j < 4; j++)
#pragma unroll
            for (int r = 0; r < 4; r++) cacc[i][j][r] = 0.f;

    for (int j = 0; j < 16; j++) {
        if (j < 15) {
            issueK(j + 1, (j + 1) & 1);
            cp_commit();
            cp_wait<2>();
        } else {
            cp_wait<1>();
        }
        __syncthreads();

        smma(sK + (j & 1) * 128 * LDK);

        // p = exp(s)*invsum: write attn (fp32) + sP (tf32-rounded)
#pragma unroll
        for (int i = 0; i < 2; i++) {
            const int lrow = wm + 16 * i + grp;
#pragma unroll
            for (int t = 0; t < 8; t++) {
                const int col = wn + 8 * t + 2 * qid;
                float p0 = __expf(sa[i][t][0]) * rinv[i * 2 + 0];
                float p1 = __expf(sa[i][t][1]) * rinv[i * 2 + 0];
                float p2 = __expf(sa[i][t][2]) * rinv[i * 2 + 1];
                float p3 = __expf(sa[i][t][3]) * rinv[i * 2 + 1];
                *(float2*)(attng + (size_t)lrow * S_ + (size_t)j * 128 + col) =
                    make_float2(p0, p1);
                *(float2*)(attng + (size_t)(lrow + 8) * S_ + (size_t)j * 128 + col) =
                    make_float2(p2, p3);
                *(float2*)(sP + lrow * LDP + col) =
                    make_float2(__uint_as_float(f2tf(p0)), __uint_as_float(f2tf(p1)));
                *(float2*)(sP + (lrow + 8) * LDP + col) =
                    make_float2(__uint_as_float(f2tf(p2)), __uint_as_float(f2tf(p3)));
            }
        }

        if (j < 15) cp_wait<1>();  // V_j ready (older than K_{j+1})
        else        cp_wait<0>();
        __syncthreads();           // sP complete + sV visible

        // ctx += P(128x128) @ V(128x64); per warp: 32 rows x 32 V-cols
#pragma unroll
        for (int ks = 0; ks < 16; ks++) {
            uint32_t afr[2][4];
#pragma unroll
            for (int i = 0; i < 2; i++) {
                const float* ap = sP + (wm + 16 * i + grp) * LDP + 8 * ks + qid;
                afr[i][0] = fbits(ap[0]);
                afr[i][1] = fbits(ap[8 * LDP]);
                afr[i][2] = fbits(ap[4]);
                afr[i][3] = fbits(ap[8 * LDP + 4]);
            }
#pragma unroll
            for (int t = 0; t < 4; t++) {
                const float* bp = sV + (8 * ks + qid) * LDV + wn2 + 8 * t + grp;
                uint32_t bfr[2] = {fbits(bp[0]), fbits(bp[4 * LDV])};
#pragma unroll
                for (int i = 0; i < 2; i++) mma8(cacc[i][t], afr[i], bfr);
            }
        }
        __syncthreads();  // sV / sP free

        if (j < 15) {
            issueV(j + 1);
            cp_commit();
        }
    }

    // write ctx (tf32-rounded: feeds output projection)
    float* ctxg = ctx + (size_t)b * S_ * D_ + h * HD_ + rowbase * D_;
#pragma unroll
    for (int i = 0; i < 2; i++) {
        const int lrow = wm + 16 * i + grp;
#pragma unroll
        for (int t = 0; t < 4; t++) {
            const int col = wn2 + 8 * t + 2 * qid;
            *(float2*)(ctxg + (size_t)lrow * D_ + col) = make_float2(
                __uint_as_float(f2tf(cacc[i][t][0])),
                __uint_as_float(f2tf(cacc[i][t][1])));
            *(float2*)(ctxg + (size_t)(lrow + 8) * D_ + col) = make_float2(
                __uint_as_float(f2tf(cacc[i][t][2])),
                __uint_as_float(f2tf(cacc[i][t][3])));
        }
    }
}

// ---------------------------------------------------------------------------
extern "C" void kernel_launch(void* const* d_in, const int* in_sizes, int n_in,
                              void* d_out, int out_size)
{
    const float* x  = (const float*)d_in[0];
    const float* Wq = (const float*)d_in[1];
    const float* bq = (const float*)d_in[2];
    const float* Wk = (const float*)d_in[3];
    const float* bk = (const float*)d_in[4];
    const float* Wv = (const float*)d_in[5];
    const float* bv = (const float*)d_in[6];
    const float* Wo = (const float*)d_in[7];
    const float* bo = (const float*)d_in[8];

    float* out = (float*)d_out;

    float *Qp, *Kp, *Vp, *Cp, *Xp, *Wr;
    cudaGetSymbolAddress((void**)&Qp, g_Q);
    cudaGetSymbolAddress((void**)&Kp, g_K);
    cudaGetSymbolAddress((void**)&Vp, g_V);
    cudaGetSymbolAddress((void**)&Cp, g_C);
    cudaGetSymbolAddress((void**)&Xp, g_X);
    cudaGetSymbolAddress((void**)&Wr, g_Wr);

    float* attn;
    if ((size_t)out_size >= BSD + BHSS) {
        attn = out + BSD;
    } else {
        cudaGetSymbolAddress((void**)&attn, g_attn_fallback);
    }

    constexpr int WN = D_ * D_;  // 1M

    // 0) pre-round x and all weights to tf32
    round_kernel<<<(int)(BSD / 4 + 255) / 256, 256>>>((const float4*)x, (float4*)Xp, (int)(BSD / 4));
    round_kernel<<<(WN / 4 + 255) / 256, 256>>>((const float4*)Wq, (float4*)(Wr + 0 * WN), WN / 4);
    round_kernel<<<(WN / 4 + 255) / 256, 256>>>((const float4*)Wk, (float4*)(Wr + 1 * WN), WN / 4);
    round_kernel<<<(WN / 4 + 255) / 256, 256>>>((const float4*)Wv, (float4*)(Wr + 2 * WN), WN / 4);
    round_kernel<<<(WN / 4 + 255) / 256, 256>>>((const float4*)Wo, (float4*)(Wr + 3 * WN), WN / 4);

    constexpr int SMEM_P = 3 * (2 * 128 * 36) * 4;  // 110592 B
    cudaFuncSetAttribute(proj_gemm<true>,
                         cudaFuncAttributeMaxDynamicSharedMemorySize, SMEM_P);
    cudaFuncSetAttribute(proj_gemm<false>,
                         cudaFuncAttributeMaxDynamicSharedMemorySize, SMEM_P);
    cudaFuncSetAttribute(attn_fused,
                         cudaFuncAttributeMaxDynamicSharedMemorySize, SM_ATT_BYTES);

    // 1) projections (Q pre-scaled by 1/8; Q,K,V rounded to tf32 at write)
    dim3 gproj(D_ / 128, (B_ * S_) / 128);  // (8, 32)
    proj_gemm<true><<<gproj, 256, SMEM_P>>>(Xp, Wr + 0 * WN, bq, Qp, D_, 0.125f);
    proj_gemm<true><<<gproj, 256, SMEM_P>>>(Xp, Wr + 1 * WN, bk, Kp, D_, 1.f);
    proj_gemm<true><<<gproj, 256, SMEM_P>>>(Xp, Wr + 2 * WN, bv, Vp, D_, 1.f);

    // 2) fused scores + softmax + ctx (attn written exactly once)
    dim3 gatt(S_ / 128, B_ * H_);  // (16, 32)
    attn_fused<<<gatt, 256, SM_ATT_BYTES>>>(Qp, Kp, Vp, attn, Cp);

    // 3) out = ctx @ Wo^T + bo (fp32 output, no rounding)
    proj_gemm<false><<<gproj, 256, SMEM_P>>>(Cp, Wr + 3 * WN, bo, out, D_, 1.f);
}

// round 4
// speedup vs baseline: 3.1173x; 1.0533x over previous
#include <cuda_runtime.h>
#include <math.h>
#include <stdint.h>

// Problem constants
constexpr int B_ = 2;
constexpr int S_ = 2048;
constexpr int D_ = 1024;
constexpr int H_ = 16;
constexpr int HD_ = 64;

constexpr size_t BSD  = (size_t)B_ * S_ * D_;          // 4,194,304
constexpr size_t BHSS = (size_t)B_ * H_ * S_ * S_;     // 134,217,728

// Scratch (device globals: allocation is forbidden)
__device__ float g_Q[BSD];
__device__ float g_K[BSD];
__device__ float g_V[BSD];
__device__ float g_C[BSD];
__device__ float g_X[BSD];                 // tf32-rounded x
__device__ float g_Wr[4 * D_ * D_];        // tf32-rounded Wq,Wk,Wv,Wo
__device__ float g_attn_fallback[BHSS];

// ---------------------------------------------------------------------------
// Helpers
// ---------------------------------------------------------------------------
__device__ __forceinline__ uint32_t f2tf(float f) {
    uint32_t u;
    asm("cvt.rna.tf32.f32 %0, %1;" : "=r"(u) : "f"(f));
    return u;
}

__device__ __forceinline__ void mma8(float* c, const uint32_t* a, const uint32_t* b) {
    asm volatile(
        "mma.sync.aligned.m16n8k8.row.col.f32.tf32.tf32.f32 "
        "{%0,%1,%2,%3},{%4,%5,%6,%7},{%8,%9},{%0,%1,%2,%3};"
        : "+f"(c[0]), "+f"(c[1]), "+f"(c[2]), "+f"(c[3])
        : "r"(a[0]), "r"(a[1]), "r"(a[2]), "r"(a[3]), "r"(b[0]), "r"(b[1]));
}

__device__ __forceinline__ void cp16(uint32_t saddr, const void* gaddr) {
    asm volatile("cp.async.cg.shared.global [%0], [%1], 16;" :: "r"(saddr), "l"(gaddr));
}
__device__ __forceinline__ void cp_commit() {
    asm volatile("cp.async.commit_group;");
}
template <int N>
__device__ __forceinline__ void cp_wait() {
    asm volatile("cp.async.wait_group %0;" :: "n"(N));
}

__device__ __forceinline__ uint32_t fbits(float f) { return __float_as_uint(f); }

// ---------------------------------------------------------------------------
// tf32 pre-round kernel (elementwise, float4)
// ---------------------------------------------------------------------------
__global__ void round_kernel(const float4* __restrict__ in, float4* __restrict__ out, int n4)
{
    int i = blockIdx.x * blockDim.x + threadIdx.x;
    if (i < n4) {
        float4 v = in[i];
        float4 o;
        o.x = __uint_as_float(f2tf(v.x));
        o.y = __uint_as_float(f2tf(v.y));
        o.z = __uint_as_float(f2tf(v.z));
        o.w = __uint_as_float(f2tf(v.w));
        out[i] = o;
    }
}

// ---------------------------------------------------------------------------
// NT projection GEMM: C[M,N] = alpha*(A[M,K] @ Bm[N,K]^T + bias[N])
// Inputs already tf32-rounded -> no cvt in mainloop.
// Tile 128x128x32, 256 threads (4x2 warps), 3-stage cp.async pipeline.
// ---------------------------------------------------------------------------
template <bool ROUND>
__global__ __launch_bounds__(256, 2) void proj_gemm(
    const float* __restrict__ A, const float* __restrict__ Bm,
    const float* __restrict__ bias, float* __restrict__ C,
    int K, float alpha)
{
    constexpr int LD = 36;
    constexpr int A_WORDS = 128 * LD;
    constexpr int STAGE = 2 * A_WORDS;
    constexpr int NS = 3;
    extern __shared__ float smem[];

    const int tid = threadIdx.x;
    const size_t bm = (size_t)blockIdx.y * 128;
    const size_t bn = (size_t)blockIdx.x * 128;
    const int T = K / 32;

    auto issue = [&](int t, int s) {
        const int k0 = t * 32;
        float* As = smem + s * STAGE;
        float* Bs = As + A_WORDS;
#pragma unroll
        for (int i = 0; i < 4; i++) {
            int f = tid + 256 * i;
            int m = f >> 3;
            int kc = (f & 7) * 4;
            cp16((uint32_t)__cvta_generic_to_shared(As + m * LD + kc),
                 A + (bm + m) * (size_t)D_ + k0 + kc);
            cp16((uint32_t)__cvta_generic_to_shared(Bs + m * LD + kc),
                 Bm + (bn + m) * (size_t)D_ + k0 + kc);
        }
    };

#pragma unroll
    for (int s = 0; s < NS - 1; s++) {
        issue(s, s);
        cp_commit();
    }

    const int warp = tid >> 5, lane = tid & 31;
    const int wm = (warp >> 1) * 32;
    const int wn = (warp & 1) * 64;
    const int grp = lane >> 2, qid = lane & 3;

    float acc[2][8][4];
#pragma unroll
    for (int i = 0; i < 2; i++)
#pragma unroll
        for (int j = 0; j < 8; j++)
#pragma unroll
            for (int r = 0; r < 4; r++) acc[i][j][r] = 0.f;

    for (int t = 0; t < T; t++) {
        cp_wait<NS - 2>();
        __syncthreads();
        const float* As = smem + (t % NS) * STAGE;
        const float* Bs = As + A_WORDS;

#pragma unroll
        for (int ks = 0; ks < 4; ks++) {
            uint32_t afr[2][4];
#pragma unroll
            for (int i = 0; i < 2; i++) {
                const float* ap = As + (wm + 16 * i + grp) * LD + 8 * ks + qid;
                afr[i][0] = fbits(ap[0]);
                afr[i][1] = fbits(ap[8 * LD]);
                afr[i][2] = fbits(ap[4]);
                afr[i][3] = fbits(ap[8 * LD + 4]);
            }
#pragma unroll
            for (int j = 0; j < 8; j++) {
                const float* bp = Bs + (wn + 8 * j + grp) * LD + 8 * ks + qid;
                uint32_t bfr[2] = {fbits(bp[0]), fbits(bp[4])};
#pragma unroll
                for (int i = 0; i < 2; i++) mma8(acc[i][j], afr[i], bfr);
            }
        }
        if (t + NS - 1 < T) issue(t + NS - 1, (t + NS - 1) % NS);
        cp_commit();
        __syncthreads();
    }

#pragma unroll
    for (int i = 0; i < 2; i++) {
#pragma unroll
        for (int j = 0; j < 8; j++) {
            size_t row = bm + wm + 16 * i + grp;
            size_t col = bn + wn + 8 * j + 2 * qid;
            float bx = bias[col], by = bias[col + 1];
            float v0 = (acc[i][j][0] + bx) * alpha;
            float v1 = (acc[i][j][1] + by) * alpha;
            float v2 = (acc[i][j][2] + bx) * alpha;
            float v3 = (acc[i][j][3] + by) * alpha;
            if (ROUND) {
                v0 = __uint_as_float(f2tf(v0));
                v1 = __uint_as_float(f2tf(v1));
                v2 = __uint_as_float(f2tf(v2));
                v3 = __uint_as_float(f2tf(v3));
            }
            *(float2*)(C + row * (size_t)D_ + col) = make_float2(v0, v1);
            *(float2*)(C + (row + 8) * (size_t)D_ + col) = make_float2(v2, v3);
        }
    }
}

// ---------------------------------------------------------------------------
// Fused attention v2: CTA = (b,h) x 128 query rows; 8 warps x 16 rows each.
// Warp-local everything: Q fragments in registers, PV contraction warp-local
// (S c-frag -> PV a-frag via quad shuffles), no P staging in smem.
// Pass A: stream 64-key tiles, rowsum of exp(S). (registers only)
// Pass B: recompute S, write attn once, accumulate ctx = P@V.
// K,V double-buffered 64-key tiles in one cp.async group; 2 CTAs/SM.
// ---------------------------------------------------------------------------
constexpr int KT = 64;            // keys per tile
constexpr int NT_TILES = S_ / KT; // 32
constexpr int LDK2 = 68;
constexpr int LDV2 = 72;
constexpr int KWORDS = KT * LDK2;   // 4352
constexpr int VWORDS = KT * LDV2;   // 4608
constexpr int SM_ATT_BYTES = (2 * KWORDS + 2 * VWORDS) * 4;  // 71680

__global__ __launch_bounds__(256, 2) void attn_fused(
    const float* __restrict__ Q, const float* __restrict__ K,
    const float* __restrict__ V, float* __restrict__ attn,
    float* __restrict__ ctx)
{
    extern __shared__ float sm[];
    float* sK = sm;
    float* sV = sm + 2 * KWORDS;

    const int tid = threadIdx.x;
    const int warp = tid >> 5, lane = tid & 31;
    const int grp = lane >> 2, qid = lane & 3;
    const int wm = warp * 16;

    const int z = blockIdx.y;
    const int b = z >> 4, h = z & 15;
    const size_t rowbase = (size_t)blockIdx.x * 128;
    const float* Qg = Q + (size_t)b * S_ * D_ + h * HD_ + rowbase * D_;
    const float* Kg = K + (size_t)b * S_ * D_ + h * HD_;
    const float* Vg = V + (size_t)b * S_ * D_ + h * HD_;
    float* attng = attn + (size_t)z * S_ * S_ + rowbase * S_;

    // ---- Q fragments in registers (16 rows per warp, 64 cols) ----
    uint32_t qa[8][4];
    {
        const float* q0 = Qg + (size_t)(wm + grp) * D_ + qid;
        const float* q1 = Qg + (size_t)(wm + grp + 8) * D_ + qid;
#pragma unroll
        for (int ks = 0; ks < 8; ks++) {
            qa[ks][0] = fbits(q0[8 * ks]);
            qa[ks][1] = fbits(q1[8 * ks]);
            qa[ks][2] = fbits(q0[8 * ks + 4]);
            qa[ks][3] = fbits(q1[8 * ks + 4]);
        }
    }

    // cp.async issuers: per tile t, 64 rows x 16 float4 each for K and V
    auto issueK = [&](int t, int buf) {
        float* kd = sK + buf * KWORDS;
        const float* ksrc = Kg + (size_t)t * KT * D_;
#pragma unroll
        for (int i = 0; i < 4; i++) {
            int f = tid + 256 * i;
            int r = f >> 4;
            int c = (f & 15) * 4;
            cp16((uint32_t)__cvta_generic_to_shared(kd + r * LDK2 + c),
                 ksrc + (size_t)r * D_ + c);
        }
    };
    auto issueV = [&](int t, int buf) {
        float* vd = sV + buf * VWORDS;
        const float* vsrc = Vg + (size_t)t * KT * D_;
#pragma unroll
        for (int i = 0; i < 4; i++) {
            int f = tid + 256 * i;
            int r = f >> 4;
            int c = (f & 15) * 4;
            cp16((uint32_t)__cvta_generic_to_shared(vd + r * LDV2 + c),
                 vsrc + (size_t)r * D_ + c);
        }
    };

    // ================= Pass A: row sums of exp(S) =================
    float rsum0 = 0.f, rsum1 = 0.f;

    issueK(0, 0); cp_commit();
    issueK(1, 1); cp_commit();
    for (int t = 0; t < NT_TILES; t++) {
        cp_wait<1>();
        __syncthreads();
        const float* Ks = sK + (t & 1) * KWORDS;
#pragma unroll
        for (int jj = 0; jj < 8; jj++) {
            float c[4] = {0.f, 0.f, 0.f, 0.f};
#pragma unroll
            for (int ks = 0; ks < 8; ks++) {
                const float* bp = Ks + (8 * jj + grp) * LDK2 + 8 * ks + qid;
                uint32_t bfr[2] = {fbits(bp[0]), fbits(bp[4])};
                mma8(c, qa[ks], bfr);
            }
            rsum0 += __expf(c[0]) + __expf(c[1]);
            rsum1 += __expf(c[2]) + __expf(c[3]);
        }
        __syncthreads();
        if (t + 2 < NT_TILES) issueK(t + 2, t & 1);
        cp_commit();
    }
    cp_wait<0>();

    // reduce across the quad (cols are partitioned by qid within each jj)
    rsum0 += __shfl_xor_sync(0xffffffffu, rsum0, 1);
    rsum0 += __shfl_xor_sync(0xffffffffu, rsum0, 2);
    rsum1 += __shfl_xor_sync(0xffffffffu, rsum1, 1);
    rsum1 += __shfl_xor_sync(0xffffffffu, rsum1, 2);
    const float rinv0 = 1.f / rsum0;
    const float rinv1 = 1.f / rsum1;
    __syncthreads();

    // ================= Pass B: attn write + ctx = P @ V =================
    float cacc[8][4];
#pragma unroll
    for (int t = 0; t < 8; t++)
#pragma unroll
        for (int r = 0; r < 4; r++) cacc[t][r] = 0.f;

    issueK(0, 0); issueV(0, 0); cp_commit();
    issueK(1, 1); issueV(1, 1); cp_commit();

    const int src0 = grp * 4 + (qid >> 1);
    const int src1 = src0 + 2;
    const bool odd = (qid & 1);

    for (int t = 0; t < NT_TILES; t++) {
        cp_wait<1>();
        __syncthreads();
        const float* Ks = sK + (t & 1) * KWORDS;
        const float* Vs = sV + (t & 1) * VWORDS;

#pragma unroll
        for (int jj = 0; jj < 8; jj++) {
            float c[4] = {0.f, 0.f, 0.f, 0.f};
#pragma unroll
            for (int ks = 0; ks < 8; ks++) {
                const float* bp = Ks + (8 * jj + grp) * LDK2 + 8 * ks + qid;
                uint32_t bfr[2] = {fbits(bp[0]), fbits(bp[4])};
                mma8(c, qa[ks], bfr);
            }
            float p0 = __expf(c[0]) * rinv0;
            float p1 = __expf(c[1]) * rinv0;
            float p2 = __expf(c[2]) * rinv1;
            float p3 = __expf(c[3]) * rinv1;

            const size_t colb = (size_t)t * KT + 8 * jj + 2 * qid;
            *(float2*)(attng + (size_t)(wm + grp) * S_ + colb) = make_float2(p0, p1);
            *(float2*)(attng + (size_t)(wm + grp + 8) * S_ + colb) = make_float2(p2, p3);

            // c-frag -> PV a-frag (tf32), via quad shuffles
            uint32_t e0 = f2tf(p0), o0 = f2tf(p1);
            uint32_t e1 = f2tf(p2), o1 = f2tf(p3);
            uint32_t xe = __shfl_sync(0xffffffffu, e0, src0);
            uint32_t xo = __shfl_sync(0xffffffffu, o0, src0);
            uint32_t a0 = odd ? xo : xe;
            xe = __shfl_sync(0xffffffffu, e1, src0);
            xo = __shfl_sync(0xffffffffu, o1, src0);
            uint32_t a1 = odd ? xo : xe;
            xe = __shfl_sync(0xffffffffu, e0, src1);
            xo = __shfl_sync(0xffffffffu, o0, src1);
            uint32_t a2 = odd ? xo : xe;
            xe = __shfl_sync(0xffffffffu, e1, src1);
            xo = __shfl_sync(0xffffffffu, o1, src1);
            uint32_t a3 = odd ? xo : xe;
            uint32_t pa[4] = {a0, a1, a2, a3};

            const float* vrow = Vs + (8 * jj + qid) * LDV2;
#pragma unroll
            for (int tt = 0; tt < 8; tt++) {
                const float* bp = vrow + 8 * tt + grp;
                uint32_t bfr[2] = {fbits(bp[0]), fbits(bp[4 * LDV2])};
                mma8(cacc[tt], pa, bfr);
            }
        }
        __syncthreads();
        if (t + 2 < NT_TILES) { issueK(t + 2, t & 1); issueV(t + 2, t & 1); }
        cp_commit();
    }

    // write ctx (tf32-rounded: feeds output projection)
    float* ctxg = ctx + (size_t)b * S_ * D_ + h * HD_ + rowbase * D_;
#pragma unroll
    for (int tt = 0; tt < 8; tt++) {
        const int col = 8 * tt + 2 * qid;
        *(float2*)(ctxg + (size_t)(wm + grp) * D_ + col) = make_float2(
            __uint_as_float(f2tf(cacc[tt][0])),
            __uint_as_float(f2tf(cacc[tt][1])));
        *(float2*)(ctxg + (size_t)(wm + grp + 8) * D_ + col) = make_float2(
            __uint_as_float(f2tf(cacc[tt][2])),
            __uint_as_float(f2tf(cacc[tt][3])));
    }
}

// ---------------------------------------------------------------------------
extern "C" void kernel_launch(void* const* d_in, const int* in_sizes, int n_in,
                              void* d_out, int out_size)
{
    const float* x  = (const float*)d_in[0];
    const float* Wq = (const float*)d_in[1];
    const float* bq = (const float*)d_in[2];
    const float* Wk = (const float*)d_in[3];
    const float* bk = (const float*)d_in[4];
    const float* Wv = (const float*)d_in[5];
    const float* bv = (const float*)d_in[6];
    const float* Wo = (const float*)d_in[7];
    const float* bo = (const float*)d_in[8];

    float* out = (float*)d_out;

    float *Qp, *Kp, *Vp, *Cp, *Xp, *Wr;
    cudaGetSymbolAddress((void**)&Qp, g_Q);
    cudaGetSymbolAddress((void**)&Kp, g_K);
    cudaGetSymbolAddress((void**)&Vp, g_V);
    cudaGetSymbolAddress((void**)&Cp, g_C);
    cudaGetSymbolAddress((void**)&Xp, g_X);
    cudaGetSymbolAddress((void**)&Wr, g_Wr);

    float* attn;
    if ((size_t)out_size >= BSD + BHSS) {
        attn = out + BSD;
    } else {
        cudaGetSymbolAddress((void**)&attn, g_attn_fallback);
    }

    constexpr int WN = D_ * D_;  // 1M

    // 0) pre-round x and all weights to tf32
    round_kernel<<<(int)(BSD / 4 + 255) / 256, 256>>>((const float4*)x, (float4*)Xp, (int)(BSD / 4));
    round_kernel<<<(WN / 4 + 255) / 256, 256>>>((const float4*)Wq, (float4*)(Wr + 0 * WN), WN / 4);
    round_kernel<<<(WN / 4 + 255) / 256, 256>>>((const float4*)Wk, (float4*)(Wr + 1 * WN), WN / 4);
    round_kernel<<<(WN / 4 + 255) / 256, 256>>>((const float4*)Wv, (float4*)(Wr + 2 * WN), WN / 4);
    round_kernel<<<(WN / 4 + 255) / 256, 256>>>((const float4*)Wo, (float4*)(Wr + 3 * WN), WN / 4);

    constexpr int SMEM_P = 3 * (2 * 128 * 36) * 4;  // 110592 B
    cudaFuncSetAttribute(proj_gemm<true>,
                         cudaFuncAttributeMaxDynamicSharedMemorySize, SMEM_P);
    cudaFuncSetAttribute(proj_gemm<false>,
                         cudaFuncAttributeMaxDynamicSharedMemorySize, SMEM_P);
    cudaFuncSetAttribute(attn_fused,
                         cudaFuncAttributeMaxDynamicSharedMemorySize, SM_ATT_BYTES);

    // 1) projections (Q pre-scaled by 1/8; Q,K,V rounded to tf32 at write)
    dim3 gproj(D_ / 128, (B_ * S_) / 128);  // (8, 32)
    proj_gemm<true><<<gproj, 256, SMEM_P>>>(Xp, Wr + 0 * WN, bq, Qp, D_, 0.125f);
    proj_gemm<true><<<gproj, 256, SMEM_P>>>(Xp, Wr + 1 * WN, bk, Kp, D_, 1.f);
    proj_gemm<true><<<gproj, 256, SMEM_P>>>(Xp, Wr + 2 * WN, bv, Vp, D_, 1.f);

    // 2) fused scores + softmax + ctx (attn written exactly once)
    dim3 gatt(S_ / 128, B_ * H_);  // (16, 32)
    attn_fused<<<gatt, 256, SM_ATT_BYTES>>>(Qp, Kp, Vp, attn, Cp);

    // 3) out = ctx @ Wo^T + bo (fp32 output, no rounding)
    proj_gemm<false><<<gproj, 256, SMEM_P>>>(Cp, Wr + 3 * WN, bo, out, D_, 1.f);
}

// round 5
// speedup vs baseline: 5.2405x; 1.6811x over previous
#include <cuda_runtime.h>
#include <cuda_fp16.h>
#include <math.h>
#include <stdint.h>

// Problem constants
constexpr int B_ = 2;
constexpr int S_ = 2048;
constexpr int D_ = 1024;
constexpr int H_ = 16;
constexpr int HD_ = 64;

constexpr size_t BSD  = (size_t)B_ * S_ * D_;          // 4,194,304
constexpr size_t BHSS = (size_t)B_ * H_ * S_ * S_;     // 134,217,728

// Scratch (device globals: allocation is forbidden)
__device__ __half g_Qh[BSD];
__device__ __half g_Kh[BSD];
__device__ __half g_Vh[BSD];
__device__ __half g_Ch[BSD];
__device__ __half g_Xh[BSD];               // fp16 x
__device__ __half g_Wh[4 * D_ * D_];       // fp16 Wq,Wk,Wv,Wo
__device__ float g_attn_fallback[BHSS];

// ---------------------------------------------------------------------------
// Helpers
// ---------------------------------------------------------------------------
__device__ __forceinline__ uint32_t ld32h(const __half* p) {
    return *reinterpret_cast<const uint32_t*>(p);
}
__device__ __forceinline__ uint32_t packh2(float a, float b) {
    __half2 h = __floats2half2_rn(a, b);
    return *reinterpret_cast<uint32_t*>(&h);
}

__device__ __forceinline__ void hmma(float* c, const uint32_t* a, uint32_t b0, uint32_t b1) {
    asm volatile(
        "mma.sync.aligned.m16n8k16.row.col.f32.f16.f16.f32 "
        "{%0,%1,%2,%3},{%4,%5,%6,%7},{%8,%9},{%0,%1,%2,%3};"
        : "+f"(c[0]), "+f"(c[1]), "+f"(c[2]), "+f"(c[3])
        : "r"(a[0]), "r"(a[1]), "r"(a[2]), "r"(a[3]), "r"(b0), "r"(b1));
}

__device__ __forceinline__ void ldsm4(uint32_t& r0, uint32_t& r1, uint32_t& r2, uint32_t& r3,
                                      uint32_t addr) {
    asm volatile("ldmatrix.sync.aligned.m8n8.x4.shared.b16 {%0,%1,%2,%3}, [%4];"
                 : "=r"(r0), "=r"(r1), "=r"(r2), "=r"(r3) : "r"(addr));
}
__device__ __forceinline__ void ldsm4t(uint32_t& r0, uint32_t& r1, uint32_t& r2, uint32_t& r3,
                                       uint32_t addr) {
    asm volatile("ldmatrix.sync.aligned.m8n8.x4.trans.shared.b16 {%0,%1,%2,%3}, [%4];"
                 : "=r"(r0), "=r"(r1), "=r"(r2), "=r"(r3) : "r"(addr));
}

__device__ __forceinline__ void cp16(uint32_t saddr, const void* gaddr) {
    asm volatile("cp.async.cg.shared.global [%0], [%1], 16;" :: "r"(saddr), "l"(gaddr));
}
__device__ __forceinline__ void cp_commit() {
    asm volatile("cp.async.commit_group;");
}
template <int N>
__device__ __forceinline__ void cp_wait() {
    asm volatile("cp.async.wait_group %0;" :: "n"(N));
}

// ---------------------------------------------------------------------------
// fp32 -> fp16 conversion kernel (4 floats -> 4 halves per thread)
// ---------------------------------------------------------------------------
__global__ void tohalf_kernel(const float4* __restrict__ in, uint2* __restrict__ out, int n4)
{
    int i = blockIdx.x * blockDim.x + threadIdx.x;
    if (i < n4) {
        float4 v = in[i];
        uint2 o;
        o.x = packh2(v.x, v.y);
        o.y = packh2(v.z, v.w);
        out[i] = o;
    }
}

// ---------------------------------------------------------------------------
// fp16 NT projection GEMM: C[M,N] = alpha*(A[M,K] @ Bm[N,K]^T + bias[N])
// Tile 128x128x32, 256 threads (4x2 warps), 4-stage cp.async, m16n8k16.
// OUTF32: write fp32 (final output) else fp16 (Q/K/V/ctx).
// ---------------------------------------------------------------------------
template <bool OUTF32>
__global__ __launch_bounds__(256, 2) void proj_h(
    const __half* __restrict__ A, const __half* __restrict__ Bm,
    const float* __restrict__ bias, void* __restrict__ Cout, float alpha)
{
    constexpr int LD = 40;                 // 32 k + 8 pad (halves)
    constexpr int AW = 128 * LD;           // halves
    constexpr int STAGE = 2 * AW;
    constexpr int NS = 4;
    extern __shared__ __half smh[];

    const int tid = threadIdx.x;
    const size_t bm = (size_t)blockIdx.y * 128;
    const size_t bn = (size_t)blockIdx.x * 128;
    constexpr int T = D_ / 32;             // 32 k-tiles

    auto issue = [&](int t, int s) {
        const int k0 = t * 32;
        __half* As = smh + s * STAGE;
        __half* Bs = As + AW;
#pragma unroll
        for (int i = 0; i < 2; i++) {
            int f = tid + 256 * i;
            int r = f >> 2;
            int c = (f & 3) * 8;
            cp16((uint32_t)__cvta_generic_to_shared(As + r * LD + c),
                 A + (bm + r) * (size_t)D_ + k0 + c);
            cp16((uint32_t)__cvta_generic_to_shared(Bs + r * LD + c),
                 Bm + (bn + r) * (size_t)D_ + k0 + c);
        }
    };

#pragma unroll
    for (int s = 0; s < NS - 1; s++) {
        issue(s, s);
        cp_commit();
    }

    const int warp = tid >> 5, lane = tid & 31;
    const int wm = (warp >> 1) * 32;
    const int wn = (warp & 1) * 64;
    const int grp = lane >> 2, qid = lane & 3;

    float acc[2][8][4];
#pragma unroll
    for (int i = 0; i < 2; i++)
#pragma unroll
        for (int j = 0; j < 8; j++)
#pragma unroll
            for (int r = 0; r < 4; r++) acc[i][j][r] = 0.f;

    for (int t = 0; t < T; t++) {
        cp_wait<NS - 2>();
        __syncthreads();
        const __half* As = smh + (t % NS) * STAGE;
        const __half* Bs = As + AW;

#pragma unroll
        for (int ks = 0; ks < 2; ks++) {
            uint32_t afr[2][4];
#pragma unroll
            for (int i = 0; i < 2; i++) {
                const __half* ap = As + (wm + 16 * i + grp) * LD + 16 * ks + 2 * qid;
                afr[i][0] = ld32h(ap);
                afr[i][1] = ld32h(ap + 8 * LD);
                afr[i][2] = ld32h(ap + 8);
                afr[i][3] = ld32h(ap + 8 * LD + 8);
            }
#pragma unroll
            for (int j = 0; j < 8; j++) {
                const __half* bp = Bs + (wn + 8 * j + grp) * LD + 16 * ks + 2 * qid;
                uint32_t b0 = ld32h(bp), b1 = ld32h(bp + 8);
#pragma unroll
                for (int i = 0; i < 2; i++) hmma(acc[i][j], afr[i], b0, b1);
            }
        }
        if (t + NS - 1 < T) issue(t + NS - 1, (t + NS - 1) % NS);
        cp_commit();
    }

#pragma unroll
    for (int i = 0; i < 2; i++) {
#pragma unroll
        for (int j = 0; j < 8; j++) {
            size_t row = bm + wm + 16 * i + grp;
            size_t col = bn + wn + 8 * j + 2 * qid;
            float bx = bias[col], by = bias[col + 1];
            float v0 = (acc[i][j][0] + bx) * alpha;
            float v1 = (acc[i][j][1] + by) * alpha;
            float v2 = (acc[i][j][2] + bx) * alpha;
            float v3 = (acc[i][j][3] + by) * alpha;
            if (OUTF32) {
                float* C = (float*)Cout;
                *(float2*)(C + row * (size_t)D_ + col) = make_float2(v0, v1);
                *(float2*)(C + (row + 8) * (size_t)D_ + col) = make_float2(v2, v3);
            } else {
                __half* C = (__half*)Cout;
                *(uint32_t*)(C + row * (size_t)D_ + col) = packh2(v0, v1);
                *(uint32_t*)(C + (row + 8) * (size_t)D_ + col) = packh2(v2, v3);
            }
        }
    }
}

// ---------------------------------------------------------------------------
// Fused fp16 attention: CTA = (b,h) x 128 query rows; 8 warps x 16 rows.
// Q in registers; K b-frags via ldmatrix; V b-frags via ldmatrix.trans;
// PV a-frags are a pure register repack of the S c-frags (no shuffles).
// Pass A: rowsum of exp(S). Pass B: recompute S, write attn once, ctx += P@V.
// ---------------------------------------------------------------------------
constexpr int KT = 64;            // keys per tile
constexpr int NT_TILES = S_ / KT; // 32
constexpr int LDK2 = 72;          // halves (64 + 8 pad)
constexpr int LDV2 = 72;
constexpr int KW = KT * LDK2;     // 4608 halves
constexpr int VW = KT * LDV2;     // 4608 halves
constexpr int SM_ATT_BYTES = (2 * KW + 2 * VW) * 2;  // 36864 B

__global__ __launch_bounds__(256) void attn_h(
    const __half* __restrict__ Q, const __half* __restrict__ K,
    const __half* __restrict__ V, float* __restrict__ attn,
    __half* __restrict__ ctx)
{
    extern __shared__ __half smh[];
    __half* sK = smh;
    __half* sV = smh + 2 * KW;

    const int tid = threadIdx.x;
    const int warp = tid >> 5, lane = tid & 31;
    const int grp = lane >> 2, qid = lane & 3;
    const int wm = warp * 16;

    const int z = blockIdx.y;
    const int b = z >> 4, h = z & 15;
    const size_t rowbase = (size_t)blockIdx.x * 128;
    const __half* Qg = Q + (size_t)b * S_ * D_ + h * HD_ + rowbase * D_;
    const __half* Kg = K + (size_t)b * S_ * D_ + h * HD_;
    const __half* Vg = V + (size_t)b * S_ * D_ + h * HD_;
    float* attng = attn + (size_t)z * S_ * S_ + rowbase * S_;

    // Q fragments in registers: 4 k-steps of 16 dims
    uint32_t qa[4][4];
    {
        const __half* q0 = Qg + (size_t)(wm + grp) * D_;
        const __half* q1 = Qg + (size_t)(wm + grp + 8) * D_;
#pragma unroll
        for (int ks = 0; ks < 4; ks++) {
            qa[ks][0] = ld32h(q0 + 16 * ks + 2 * qid);
            qa[ks][1] = ld32h(q1 + 16 * ks + 2 * qid);
            qa[ks][2] = ld32h(q0 + 16 * ks + 2 * qid + 8);
            qa[ks][3] = ld32h(q1 + 16 * ks + 2 * qid + 8);
        }
    }

    auto issueK = [&](int t, int buf) {
        __half* kd = sK + buf * KW;
        const __half* ksrc = Kg + (size_t)t * KT * D_;
#pragma unroll
        for (int i = 0; i < 2; i++) {
            int f = tid + 256 * i;
            int r = f >> 3;
            int c = (f & 7) * 8;
            cp16((uint32_t)__cvta_generic_to_shared(kd + r * LDK2 + c),
                 ksrc + (size_t)r * D_ + c);
        }
    };
    auto issueV = [&](int t, int buf) {
        __half* vd = sV + buf * VW;
        const __half* vsrc = Vg + (size_t)t * KT * D_;
#pragma unroll
        for (int i = 0; i < 2; i++) {
            int f = tid + 256 * i;
            int r = f >> 3;
            int c = (f & 7) * 8;
            cp16((uint32_t)__cvta_generic_to_shared(vd + r * LDV2 + c),
                 vsrc + (size_t)r * D_ + c);
        }
    };

    // S c-frag for one 8-key block jj (16 rows x 8 keys)
    auto smma = [&](const __half* Ks, int jj, float* c) {
        c[0] = c[1] = c[2] = c[3] = 0.f;
        const __half* kp = Ks + (jj * 8 + (lane & 7)) * LDK2 + ((lane >> 3) * 8);
        uint32_t m0, m1, m2, m3;
        ldsm4(m0, m1, m2, m3, (uint32_t)__cvta_generic_to_shared(kp));
        hmma(c, qa[0], m0, m1);
        hmma(c, qa[1], m2, m3);
        ldsm4(m0, m1, m2, m3, (uint32_t)__cvta_generic_to_shared(kp + 32));
        hmma(c, qa[2], m0, m1);
        hmma(c, qa[3], m2, m3);
    };

    // ================= Pass A: row sums of exp(S) =================
    float rsum0 = 0.f, rsum1 = 0.f;

    issueK(0, 0); cp_commit();
    issueK(1, 1); cp_commit();
    for (int t = 0; t < NT_TILES; t++) {
        cp_wait<1>();
        __syncthreads();
        const __half* Ks = sK + (t & 1) * KW;
#pragma unroll
        for (int jj = 0; jj < 8; jj++) {
            float c[4];
            smma(Ks, jj, c);
            rsum0 += __expf(c[0]) + __expf(c[1]);
            rsum1 += __expf(c[2]) + __expf(c[3]);
        }
        __syncthreads();
        if (t + 2 < NT_TILES) issueK(t + 2, t & 1);
        cp_commit();
    }
    cp_wait<0>();

    rsum0 += __shfl_xor_sync(0xffffffffu, rsum0, 1);
    rsum0 += __shfl_xor_sync(0xffffffffu, rsum0, 2);
    rsum1 += __shfl_xor_sync(0xffffffffu, rsum1, 1);
    rsum1 += __shfl_xor_sync(0xffffffffu, rsum1, 2);
    const float rinv0 = 1.f / rsum0;
    const float rinv1 = 1.f / rsum1;
    __syncthreads();

    // ================= Pass B: attn write + ctx = P @ V =================
    float cacc[8][4];
#pragma unroll
    for (int t = 0; t < 8; t++)
#pragma unroll
        for (int r = 0; r < 4; r++) cacc[t][r] = 0.f;

    issueK(0, 0); issueV(0, 0); cp_commit();
    issueK(1, 1); issueV(1, 1); cp_commit();

    for (int t = 0; t < NT_TILES; t++) {
        cp_wait<1>();
        __syncthreads();
        const __half* Ks = sK + (t & 1) * KW;
        const __half* Vs = sV + (t & 1) * VW;

#pragma unroll
        for (int jjp = 0; jjp < 4; jjp++) {
            uint32_t pa[4];
#pragma unroll
            for (int half_idx = 0; half_idx < 2; half_idx++) {
                const int jj = 2 * jjp + half_idx;
                float c[4];
                smma(Ks, jj, c);
                float p0 = __expf(c[0]) * rinv0;
                float p1 = __expf(c[1]) * rinv0;
                float p2 = __expf(c[2]) * rinv1;
                float p3 = __expf(c[3]) * rinv1;
                const size_t colb = (size_t)t * KT + jj * 8 + 2 * qid;
                *(float2*)(attng + (size_t)(wm + grp) * S_ + colb) = make_float2(p0, p1);
                *(float2*)(attng + (size_t)(wm + grp + 8) * S_ + colb) = make_float2(p2, p3);
                pa[2 * half_idx + 0] = packh2(p0, p1);
                pa[2 * half_idx + 1] = packh2(p2, p3);
            }
            // PV: k-step = 16 keys (this jj pair); V b-frags via ldmatrix.trans
            const int m = lane >> 3;
            const int keyr = 16 * jjp + (m & 1) * 8 + (lane & 7);
            const int dimo = (m >> 1) * 8;
#pragma unroll
            for (int nb = 0; nb < 4; nb++) {
                const __half* vp = Vs + keyr * LDV2 + nb * 16 + dimo;
                uint32_t r0, r1, r2, r3;
                ldsm4t(r0, r1, r2, r3, (uint32_t)__cvta_generic_to_shared(vp));
                hmma(cacc[2 * nb + 0], pa, r0, r1);
                hmma(cacc[2 * nb + 1], pa, r2, r3);
            }
        }
        __syncthreads();
        if (t + 2 < NT_TILES) { issueK(t + 2, t & 1); issueV(t + 2, t & 1); }
        cp_commit();
    }

    // write ctx (fp16: feeds output projection)
    __half* ctxg = ctx + (size_t)b * S_ * D_ + h * HD_ + rowbase * D_;
#pragma unroll
    for (int tt = 0; tt < 8; tt++) {
        const int col = 8 * tt + 2 * qid;
        *(uint32_t*)(ctxg + (size_t)(wm + grp) * D_ + col) =
            packh2(cacc[tt][0], cacc[tt][1]);
        *(uint32_t*)(ctxg + (size_t)(wm + grp + 8) * D_ + col) =
            packh2(cacc[tt][2], cacc[tt][3]);
    }
}

// ---------------------------------------------------------------------------
extern "C" void kernel_launch(void* const* d_in, const int* in_sizes, int n_in,
                              void* d_out, int out_size)
{
    const float* x  = (const float*)d_in[0];
    const float* Wq = (const float*)d_in[1];
    const float* bq = (const float*)d_in[2];
    const float* Wk = (const float*)d_in[3];
    const float* bk = (const float*)d_in[4];
    const float* Wv = (const float*)d_in[5];
    const float* bv = (const float*)d_in[6];
    const float* Wo = (const float*)d_in[7];
    const float* bo = (const float*)d_in[8];

    float* out = (float*)d_out;

    __half *Qp, *Kp, *Vp, *Cp, *Xp, *Wh;
    cudaGetSymbolAddress((void**)&Qp, g_Qh);
    cudaGetSymbolAddress((void**)&Kp, g_Kh);
    cudaGetSymbolAddress((void**)&Vp, g_Vh);
    cudaGetSymbolAddress((void**)&Cp, g_Ch);
    cudaGetSymbolAddress((void**)&Xp, g_Xh);
    cudaGetSymbolAddress((void**)&Wh, g_Wh);

    float* attn;
    if ((size_t)out_size >= BSD + BHSS) {
        attn = out + BSD;
    } else {
        cudaGetSymbolAddress((void**)&attn, g_attn_fallback);
    }

    constexpr int WN = D_ * D_;  // 1M

    // 0) convert x and all weights to fp16
    tohalf_kernel<<<(int)(BSD / 4 + 255) / 256, 256>>>((const float4*)x, (uint2*)Xp, (int)(BSD / 4));
    tohalf_kernel<<<(WN / 4 + 255) / 256, 256>>>((const float4*)Wq, (uint2*)(Wh + 0 * WN), WN / 4);
    tohalf_kernel<<<(WN / 4 + 255) / 256, 256>>>((const float4*)Wk, (uint2*)(Wh + 1 * WN), WN / 4);
    tohalf_kernel<<<(WN / 4 + 255) / 256, 256>>>((const float4*)Wv, (uint2*)(Wh + 2 * WN), WN / 4);
    tohalf_kernel<<<(WN / 4 + 255) / 256, 256>>>((const float4*)Wo, (uint2*)(Wh + 3 * WN), WN / 4);

    constexpr int SMEM_P = 4 * (2 * 128 * 40) * 2;  // 81920 B
    cudaFuncSetAttribute(proj_h<false>,
                         cudaFuncAttributeMaxDynamicSharedMemorySize, SMEM_P);
    cudaFuncSetAttribute(proj_h<true>,
                         cudaFuncAttributeMaxDynamicSharedMemorySize, SMEM_P);
    cudaFuncSetAttribute(attn_h,
                         cudaFuncAttributeMaxDynamicSharedMemorySize, SM_ATT_BYTES);

    // 1) projections (Q pre-scaled by 1/8)
    dim3 gproj(D_ / 128, (B_ * S_) / 128);  // (8, 32)
    proj_h<false><<<gproj, 256, SMEM_P>>>(Xp, Wh + 0 * WN, bq, Qp, 0.125f);
    proj_h<false><<<gproj, 256, SMEM_P>>>(Xp, Wh + 1 * WN, bk, Kp, 1.f);
    proj_h<false><<<gproj, 256, SMEM_P>>>(Xp, Wh + 2 * WN, bv, Vp, 1.f);

    // 2) fused scores + softmax + ctx (attn written exactly once)
    dim3 gatt(S_ / 128, B_ * H_);  // (16, 32)
    attn_h<<<gatt, 256, SM_ATT_BYTES>>>(Qp, Kp, Vp, attn, Cp);

    // 3) out = ctx @ Wo^T + bo (fp32 output)
    proj_h<true><<<gproj, 256, SMEM_P>>>(Cp, Wh + 3 * WN, bo, out, 1.f);
}

// round 6
// speedup vs baseline: 5.5277x; 1.0548x over previous
#include <cuda_runtime.h>
#include <cuda_fp16.h>
#include <math.h>
#include <stdint.h>

// Problem constants
constexpr int B_ = 2;
constexpr int S_ = 2048;
constexpr int D_ = 1024;
constexpr int H_ = 16;
constexpr int HD_ = 64;

constexpr size_t BSD  = (size_t)B_ * S_ * D_;          // 4,194,304
constexpr size_t BHSS = (size_t)B_ * H_ * S_ * S_;     // 134,217,728

// Scratch (device globals: allocation is forbidden)
__device__ __half g_QKVh[3 * BSD];         // Q | K | V
__device__ __half g_Ch[BSD];
__device__ __half g_Xh[BSD];               // fp16 x
__device__ __half g_Wh[4 * D_ * D_];       // fp16 Wq,Wk,Wv,Wo (contiguous)
__device__ float g_attn_fallback[BHSS];

// ---------------------------------------------------------------------------
// Helpers
// ---------------------------------------------------------------------------
__device__ __forceinline__ uint32_t packh2(float a, float b) {
    __half2 h = __floats2half2_rn(a, b);
    return *reinterpret_cast<uint32_t*>(&h);
}

__device__ __forceinline__ void hmma(float* c, const uint32_t* a, uint32_t b0, uint32_t b1) {
    asm volatile(
        "mma.sync.aligned.m16n8k16.row.col.f32.f16.f16.f32 "
        "{%0,%1,%2,%3},{%4,%5,%6,%7},{%8,%9},{%0,%1,%2,%3};"
        : "+f"(c[0]), "+f"(c[1]), "+f"(c[2]), "+f"(c[3])
        : "r"(a[0]), "r"(a[1]), "r"(a[2]), "r"(a[3]), "r"(b0), "r"(b1));
}

__device__ __forceinline__ void ldsm4(uint32_t* r, uint32_t addr) {
    asm volatile("ldmatrix.sync.aligned.m8n8.x4.shared.b16 {%0,%1,%2,%3}, [%4];"
                 : "=r"(r[0]), "=r"(r[1]), "=r"(r[2]), "=r"(r[3]) : "r"(addr));
}
__device__ __forceinline__ void ldsm4t(uint32_t& r0, uint32_t& r1, uint32_t& r2, uint32_t& r3,
                                       uint32_t addr) {
    asm volatile("ldmatrix.sync.aligned.m8n8.x4.trans.shared.b16 {%0,%1,%2,%3}, [%4];"
                 : "=r"(r0), "=r"(r1), "=r"(r2), "=r"(r3) : "r"(addr));
}

__device__ __forceinline__ void cp16(uint32_t saddr, const void* gaddr) {
    asm volatile("cp.async.cg.shared.global [%0], [%1], 16;" :: "r"(saddr), "l"(gaddr));
}
__device__ __forceinline__ void cp_commit() {
    asm volatile("cp.async.commit_group;");
}
template <int N>
__device__ __forceinline__ void cp_wait() {
    asm volatile("cp.async.wait_group %0;" :: "n"(N));
}

__device__ __forceinline__ uint32_t ld32h(const __half* p) {
    return *reinterpret_cast<const uint32_t*>(p);
}

// ---------------------------------------------------------------------------
// fp32 -> fp16 conversion kernels
// ---------------------------------------------------------------------------
__global__ void tohalf_kernel(const float4* __restrict__ in, uint2* __restrict__ out, int n4)
{
    int i = blockIdx.x * blockDim.x + threadIdx.x;
    if (i < n4) {
        float4 v = in[i];
        out[i] = make_uint2(packh2(v.x, v.y), packh2(v.z, v.w));
    }
}

// 4 weight matrices -> one contiguous fp16 buffer (n4 per matrix = 262144)
__global__ void tohalf4_kernel(const float4* __restrict__ w0, const float4* __restrict__ w1,
                               const float4* __restrict__ w2, const float4* __restrict__ w3,
                               uint2* __restrict__ out, int n4per)
{
    int i = blockIdx.x * blockDim.x + threadIdx.x;
    int total = 4 * n4per;
    if (i < total) {
        int seg = i / n4per;
        int off = i - seg * n4per;
        const float4* src = (seg == 0) ? w0 : (seg == 1) ? w1 : (seg == 2) ? w2 : w3;
        float4 v = src[off];
        out[i] = make_uint2(packh2(v.x, v.y), packh2(v.z, v.w));
    }
}

// ---------------------------------------------------------------------------
// fp16 NT GEMM with ldmatrix fragments.
// MODE 0: merged QKV projection. A = x[4096,1024], Bm = [Wq;Wk;Wv] [3072,1024].
//         grid (24, 32). Output segment seg=blockIdx.x>>3 -> QKV + seg*BSD,
//         alpha = 0.125 for Q else 1, bias chosen per segment. fp16 out.
// MODE 1: out = ctx @ Wo^T + bo, fp32 out. grid (8, 32).
// Tile 128x128x32, 256 threads (4x2 warps), 4-stage cp.async.
// ---------------------------------------------------------------------------
template <int MODE>
__global__ __launch_bounds__(256, 2) void proj2(
    const __half* __restrict__ A, const __half* __restrict__ Bm,
    const float* __restrict__ b0, const float* __restrict__ b1,
    const float* __restrict__ b2, __half* __restrict__ outh,
    float* __restrict__ outf)
{
    constexpr int LD = 40;                 // 32 k + 8 pad (halves); 80B row = 5x16B
    constexpr int AW = 128 * LD;
    constexpr int STAGE = 2 * AW;
    constexpr int NS = 4;
    extern __shared__ __half smh[];

    const int tid = threadIdx.x;
    const size_t bm = (size_t)blockIdx.y * 128;
    const size_t bn = (size_t)blockIdx.x * 128;
    constexpr int T = D_ / 32;

    auto issue = [&](int t, int s) {
        const int k0 = t * 32;
        __half* As = smh + s * STAGE;
        __half* Bs = As + AW;
#pragma unroll
        for (int i = 0; i < 2; i++) {
            int f = tid + 256 * i;
            int r = f >> 2;
            int c = (f & 3) * 8;
            cp16((uint32_t)__cvta_generic_to_shared(As + r * LD + c),
                 A + (bm + r) * (size_t)D_ + k0 + c);
            cp16((uint32_t)__cvta_generic_to_shared(Bs + r * LD + c),
                 Bm + (bn + r) * (size_t)D_ + k0 + c);
        }
    };

#pragma unroll
    for (int s = 0; s < NS - 1; s++) {
        issue(s, s);
        cp_commit();
    }

    const int warp = tid >> 5, lane = tid & 31;
    const int wm = (warp >> 1) * 32;
    const int wn = (warp & 1) * 64;
    const int grp = lane >> 2, qid = lane & 3;

    // ldmatrix lane addressing components
    const int lr8 = lane & 7;
    const int am = (lane >> 3) & 1;        // +8 rows for matrices 1,3
    const int ak = (lane >> 4) * 8;        // +8 k for matrices 2,3

    float acc[2][8][4];
#pragma unroll
    for (int i = 0; i < 2; i++)
#pragma unroll
        for (int j = 0; j < 8; j++)
#pragma unroll
            for (int r = 0; r < 4; r++) acc[i][j][r] = 0.f;

    for (int t = 0; t < T; t++) {
        cp_wait<NS - 2>();
        __syncthreads();
        const __half* As = smh + (t % NS) * STAGE;
        const __half* Bs = As + AW;

        // A fragments: 2 i-blocks x 2 ks -> 4 ldsm4
        uint32_t afr[2][2][4];
#pragma unroll
        for (int i = 0; i < 2; i++)
#pragma unroll
            for (int ks = 0; ks < 2; ks++)
                ldsm4(afr[i][ks],
                      (uint32_t)__cvta_generic_to_shared(
                          As + (wm + 16 * i + lr8 + am * 8) * LD + 16 * ks + ak));
        // B fragments: 8 j-blocks, each ldsm4 covers k0..31 -> both ks
#pragma unroll
        for (int j = 0; j < 8; j++) {
            uint32_t bfr[4];
            ldsm4(bfr, (uint32_t)__cvta_generic_to_shared(
                           Bs + (wn + 8 * j + lr8) * LD + (lane >> 3) * 8));
#pragma unroll
            for (int i = 0; i < 2; i++) {
                hmma(acc[i][j], afr[i][0], bfr[0], bfr[1]);
                hmma(acc[i][j], afr[i][1], bfr[2], bfr[3]);
            }
        }

        if (t + NS - 1 < T) issue(t + NS - 1, (t + NS - 1) % NS);
        cp_commit();
    }

    // Epilogue
    int seg = 0;
    const float* bias = b0;
    float alpha = 1.f;
    size_t ncolbase = bn;
    if (MODE == 0) {
        seg = blockIdx.x >> 3;                   // 0,1,2 -> Q,K,V
        bias = (seg == 0) ? b0 : (seg == 1) ? b1 : b2;
        alpha = (seg == 0) ? 0.125f : 1.f;
        ncolbase = bn - (size_t)seg * 1024;
    }

#pragma unroll
    for (int i = 0; i < 2; i++) {
#pragma unroll
        for (int j = 0; j < 8; j++) {
            size_t row = bm + wm + 16 * i + grp;
            size_t col = ncolbase + wn + 8 * j + 2 * qid;
            float bx = bias[col], by = bias[col + 1];
            float v0 = (acc[i][j][0] + bx) * alpha;
            float v1 = (acc[i][j][1] + by) * alpha;
            float v2 = (acc[i][j][2] + bx) * alpha;
            float v3 = (acc[i][j][3] + by) * alpha;
            if (MODE == 0) {
                __half* C = outh + (size_t)seg * BSD;
                *(uint32_t*)(C + row * (size_t)D_ + col) = packh2(v0, v1);
                *(uint32_t*)(C + (row + 8) * (size_t)D_ + col) = packh2(v2, v3);
            } else {
                *(float2*)(outf + row * (size_t)D_ + col) = make_float2(v0, v1);
                *(float2*)(outf + (row + 8) * (size_t)D_ + col) = make_float2(v2, v3);
            }
        }
    }
}

// ---------------------------------------------------------------------------
// Fused fp16 attention: CTA = (b,h) x 128 query rows; 8 warps x 16 rows.
// 128-key tiles, K/V double-buffered. Q in registers, K via ldmatrix,
// V via ldmatrix.trans, PV a-frags = register repack of S c-frags.
// Pass A: rowsum of exp(S). Pass B: recompute S, stream attn out, ctx += P@V.
// ---------------------------------------------------------------------------
constexpr int KT = 128;            // keys per tile
constexpr int NT_TILES = S_ / KT;  // 16
constexpr int LDK2 = 72;           // halves (64 + 8 pad); 144B row = 9x16B
constexpr int KW = KT * LDK2;      // 9216 halves
constexpr int SM_ATT_BYTES = 4 * KW * 2;  // 73728 B (2xK + 2xV)

__global__ __launch_bounds__(256, 2) void attn_h(
    const __half* __restrict__ Q, const __half* __restrict__ K,
    const __half* __restrict__ V, float* __restrict__ attn,
    __half* __restrict__ ctx)
{
    extern __shared__ __half smh[];
    __half* sK = smh;
    __half* sV = smh + 2 * KW;

    const int tid = threadIdx.x;
    const int warp = tid >> 5, lane = tid & 31;
    const int grp = lane >> 2, qid = lane & 3;
    const int wm = warp * 16;

    const int z = blockIdx.y;
    const int b = z >> 4, h = z & 15;
    const size_t rowbase = (size_t)blockIdx.x * 128;
    const __half* Qg = Q + (size_t)b * S_ * D_ + h * HD_ + rowbase * D_;
    const __half* Kg = K + (size_t)b * S_ * D_ + h * HD_;
    const __half* Vg = V + (size_t)b * S_ * D_ + h * HD_;
    float* attng = attn + (size_t)z * S_ * S_ + rowbase * S_;

    // Q fragments in registers: 4 k-steps of 16 dims
    uint32_t qa[4][4];
    {
        const __half* q0 = Qg + (size_t)(wm + grp) * D_;
        const __half* q1 = Qg + (size_t)(wm + grp + 8) * D_;
#pragma unroll
        for (int ks = 0; ks < 4; ks++) {
            qa[ks][0] = ld32h(q0 + 16 * ks + 2 * qid);
            qa[ks][1] = ld32h(q1 + 16 * ks + 2 * qid);
            qa[ks][2] = ld32h(q0 + 16 * ks + 2 * qid + 8);
            qa[ks][3] = ld32h(q1 + 16 * ks + 2 * qid + 8);
        }
    }

    auto issueK = [&](int t, int buf) {
        __half* kd = sK + buf * KW;
        const __half* ksrc = Kg + (size_t)t * KT * D_;
#pragma unroll
        for (int i = 0; i < 4; i++) {
            int f = tid + 256 * i;
            int r = f >> 3;
            int c = (f & 7) * 8;
            cp16((uint32_t)__cvta_generic_to_shared(kd + r * LDK2 + c),
                 ksrc + (size_t)r * D_ + c);
        }
    };
    auto issueV = [&](int t, int buf) {
        __half* vd = sV + buf * KW;
        const __half* vsrc = Vg + (size_t)t * KT * D_;
#pragma unroll
        for (int i = 0; i < 4; i++) {
            int f = tid + 256 * i;
            int r = f >> 3;
            int c = (f & 7) * 8;
            cp16((uint32_t)__cvta_generic_to_shared(vd + r * LDK2 + c),
                 vsrc + (size_t)r * D_ + c);
        }
    };

    // S c-frag for one 8-key block jj (16 rows x 8 keys)
    auto smma = [&](const __half* Ks, int jj, float* c) {
        c[0] = c[1] = c[2] = c[3] = 0.f;
        const __half* kp = Ks + (jj * 8 + (lane & 7)) * LDK2 + ((lane >> 3) * 8);
        uint32_t m[4];
        ldsm4(m, (uint32_t)__cvta_generic_to_shared(kp));
        hmma(c, qa[0], m[0], m[1]);
        hmma(c, qa[1], m[2], m[3]);
        ldsm4(m, (uint32_t)__cvta_generic_to_shared(kp + 32));
        hmma(c, qa[2], m[0], m[1]);
        hmma(c, qa[3], m[2], m[3]);
    };

    // ================= Pass A: row sums of exp(S) =================
    float rsum0 = 0.f, rsum1 = 0.f;

    issueK(0, 0); cp_commit();
    issueK(1, 1); cp_commit();
    for (int t = 0; t < NT_TILES; t++) {
        cp_wait<1>();
        __syncthreads();
        const __half* Ks = sK + (t & 1) * KW;
#pragma unroll
        for (int jj = 0; jj < 16; jj++) {
            float c[4];
            smma(Ks, jj, c);
            rsum0 += __expf(c[0]) + __expf(c[1]);
            rsum1 += __expf(c[2]) + __expf(c[3]);
        }
        __syncthreads();
        if (t + 2 < NT_TILES) issueK(t + 2, t & 1);
        cp_commit();
    }
    cp_wait<0>();

    rsum0 += __shfl_xor_sync(0xffffffffu, rsum0, 1);
    rsum0 += __shfl_xor_sync(0xffffffffu, rsum0, 2);
    rsum1 += __shfl_xor_sync(0xffffffffu, rsum1, 1);
    rsum1 += __shfl_xor_sync(0xffffffffu, rsum1, 2);
    const float rinv0 = 1.f / rsum0;
    const float rinv1 = 1.f / rsum1;
    __syncthreads();

    // ================= Pass B: attn write + ctx = P @ V =================
    float cacc[8][4];
#pragma unroll
    for (int t = 0; t < 8; t++)
#pragma unroll
        for (int r = 0; r < 4; r++) cacc[t][r] = 0.f;

    issueK(0, 0); issueV(0, 0); cp_commit();
    issueK(1, 1); issueV(1, 1); cp_commit();

    for (int t = 0; t < NT_TILES; t++) {
        cp_wait<1>();
        __syncthreads();
        const __half* Ks = sK + (t & 1) * KW;
        const __half* Vs = sV + (t & 1) * KW;

#pragma unroll
        for (int jjp = 0; jjp < 8; jjp++) {
            uint32_t pa[4];
#pragma unroll
            for (int half_idx = 0; half_idx < 2; half_idx++) {
                const int jj = 2 * jjp + half_idx;
                float c[4];
                smma(Ks, jj, c);
                float p0 = __expf(c[0]) * rinv0;
                float p1 = __expf(c[1]) * rinv0;
                float p2 = __expf(c[2]) * rinv1;
                float p3 = __expf(c[3]) * rinv1;
                const size_t colb = (size_t)t * KT + jj * 8 + 2 * qid;
                __stcs((float2*)(attng + (size_t)(wm + grp) * S_ + colb),
                       make_float2(p0, p1));
                __stcs((float2*)(attng + (size_t)(wm + grp + 8) * S_ + colb),
                       make_float2(p2, p3));
                pa[2 * half_idx + 0] = packh2(p0, p1);
                pa[2 * half_idx + 1] = packh2(p2, p3);
            }
            // PV: 16-key k-step; V b-frags via ldmatrix.trans
            const int m = lane >> 3;
            const int keyr = 16 * jjp + (m & 1) * 8 + (lane & 7);
            const int dimo = (m >> 1) * 8;
#pragma unroll
            for (int nb = 0; nb < 4; nb++) {
                const __half* vp = Vs + keyr * LDK2 + nb * 16 + dimo;
                uint32_t r0, r1, r2, r3;
                ldsm4t(r0, r1, r2, r3, (uint32_t)__cvta_generic_to_shared(vp));
                hmma(cacc[2 * nb + 0], pa, r0, r1);
                hmma(cacc[2 * nb + 1], pa, r2, r3);
            }
        }
        __syncthreads();
        if (t + 2 < NT_TILES) { issueK(t + 2, t & 1); issueV(t + 2, t & 1); }
        cp_commit();
    }

    // write ctx (fp16: feeds output projection)
    __half* ctxg = ctx + (size_t)b * S_ * D_ + h * HD_ + rowbase * D_;
#pragma unroll
    for (int tt = 0; tt < 8; tt++) {
        const int col = 8 * tt + 2 * qid;
        *(uint32_t*)(ctxg + (size_t)(wm + grp) * D_ + col) =
            packh2(cacc[tt][0], cacc[tt][1]);
        *(uint32_t*)(ctxg + (size_t)(wm + grp + 8) * D_ + col) =
            packh2(cacc[tt][2], cacc[tt][3]);
    }
}

// ---------------------------------------------------------------------------
extern "C" void kernel_launch(void* const* d_in, const int* in_sizes, int n_in,
                              void* d_out, int out_size)
{
    const float* x  = (const float*)d_in[0];
    const float* Wq = (const float*)d_in[1];
    const float* bq = (const float*)d_in[2];
    const float* Wk = (const float*)d_in[3];
    const float* bk = (const float*)d_in[4];
    const float* Wv = (const float*)d_in[5];
    const float* bv = (const float*)d_in[6];
    const float* Wo = (const float*)d_in[7];
    const float* bo = (const float*)d_in[8];

    float* out = (float*)d_out;

    __half *QKV, *Cp, *Xp, *Wh;
    cudaGetSymbolAddress((void**)&QKV, g_QKVh);
    cudaGetSymbolAddress((void**)&Cp, g_Ch);
    cudaGetSymbolAddress((void**)&Xp, g_Xh);
    cudaGetSymbolAddress((void**)&Wh, g_Wh);

    float* attn;
    if ((size_t)out_size >= BSD + BHSS) {
        attn = out + BSD;
    } else {
        cudaGetSymbolAddress((void**)&attn, g_attn_fallback);
    }

    constexpr int WN = D_ * D_;      // 1M
    constexpr int W4 = WN / 4;       // float4 per weight matrix

    // 0) convert x and all 4 weights to fp16
    tohalf_kernel<<<(int)(BSD / 4 + 255) / 256, 256>>>(
        (const float4*)x, (uint2*)Xp, (int)(BSD / 4));
    tohalf4_kernel<<<(4 * W4 + 255) / 256, 256>>>(
        (const float4*)Wq, (const float4*)Wk, (const float4*)Wv, (const float4*)Wo,
        (uint2*)Wh, W4);

    constexpr int SMEM_P = 4 * (2 * 128 * 40) * 2;  // 81920 B
    cudaFuncSetAttribute(proj2<0>, cudaFuncAttributeMaxDynamicSharedMemorySize, SMEM_P);
    cudaFuncSetAttribute(proj2<1>, cudaFuncAttributeMaxDynamicSharedMemorySize, SMEM_P);
    cudaFuncSetAttribute(attn_h, cudaFuncAttributeMaxDynamicSharedMemorySize, SM_ATT_BYTES);

    // 1) merged QKV projection: [4096, 3072] over [Wq;Wk;Wv]
    dim3 gqkv(3 * D_ / 128, (B_ * S_) / 128);  // (24, 32)
    proj2<0><<<gqkv, 256, SMEM_P>>>(Xp, Wh, bq, bk, bv, QKV, nullptr);

    // 2) fused scores + softmax + ctx (attn written exactly once, streaming)
    dim3 gatt(S_ / 128, B_ * H_);  // (16, 32)
    attn_h<<<gatt, 256, SM_ATT_BYTES>>>(QKV, QKV + BSD, QKV + 2 * BSD, attn, Cp);

    // 3) out = ctx @ Wo^T + bo (fp32 output)
    dim3 gout(D_ / 128, (B_ * S_) / 128);  // (8, 32)
    proj2<1><<<gout, 256, SMEM_P>>>(Cp, Wh + 3 * WN, bo, nullptr, nullptr, nullptr, out);
}